// round 2
// baseline (speedup 1.0000x reference)
#include <cuda_runtime.h>
#include <cstdint>
#include <cstddef>

#define BB 4
#define SS 512
#define EE 512
#define HIDD 2048
#define HH 8
#define DD 64
#define RFULL 201
#define RUSE 101
#define MR (BB*SS)   // 2048

// ---------------- scratch (static device globals; no allocation allowed) ----
__device__ float g_xn[MR*EE];
__device__ float g_x [MR*HIDD];
__device__ float g_q [MR*EE];
__device__ float g_ke[MR*EE];
__device__ float g_kv[MR*EE];
__device__ float g_krt[RFULL*EE];
__device__ float g_t1[RFULL*HH];
__device__ float g_b0t[MR*HH];
__device__ float g_P[(size_t)MR*HH*RUSE];
__device__ float g_L[(size_t)BB*HH*SS*SS];       // logits -> scores (32 MB)
__device__ float g_v [MR*EE];
__device__ float g_vn[MR*EE];
__device__ float g_h1[MR*HIDD];

// ---------------- LayerNorm: one block per row, E=512 -----------------------
__global__ void ln_kernel(const float* __restrict__ X, const float* __restrict__ g,
                          const float* __restrict__ bt, float* __restrict__ Y)
{
    int row = blockIdx.x;
    int tid = threadIdx.x; // 256
    const float* x = X + (size_t)row*EE;
    float a = x[tid], c = x[tid+256];
    float s  = a + c;
    float s2 = a*a + c*c;
    #pragma unroll
    for (int o = 16; o > 0; o >>= 1) {
        s  += __shfl_xor_sync(0xffffffffu, s,  o);
        s2 += __shfl_xor_sync(0xffffffffu, s2, o);
    }
    __shared__ float sa[8], sb[8];
    if ((tid & 31) == 0) { sa[tid>>5] = s; sb[tid>>5] = s2; }
    __syncthreads();
    float ts = 0.f, ts2 = 0.f;
    #pragma unroll
    for (int w = 0; w < 8; w++) { ts += sa[w]; ts2 += sb[w]; }
    float mean = ts * (1.f/512.f);
    float var  = ts2 * (1.f/512.f) - mean*mean;
    float r = rsqrtf(var + 1e-3f);
    Y[(size_t)row*EE + tid]       = (a-mean)*r*g[tid]     + bt[tid];
    Y[(size_t)row*EE + tid + 256] = (c-mean)*r*g[tid+256] + bt[tid+256];
}

// ---------------- SGEMM 128x128x16, 8x8 microtile, conflict-free fragments --
// EPI: 0 = +bias, 1 = +bias then relu, 2 = +bias +res
template<int EPI>
__device__ __forceinline__ void sgemm_body(
    const float* __restrict__ A, const float* __restrict__ W,
    const float* __restrict__ bias, const float* __restrict__ res,
    float* __restrict__ C, int M, int N, int K, int row0, int col0)
{
    __shared__ float As[16][128];
    __shared__ float Ws[16][128];
    int tid = threadIdx.x;          // 256
    int tx = tid & 15, ty = tid >> 4;
    float acc[8][8];
    #pragma unroll
    for (int i = 0; i < 8; i++)
        #pragma unroll
        for (int j = 0; j < 8; j++) acc[i][j] = 0.f;

    for (int k0 = 0; k0 < K; k0 += 16) {
        __syncthreads();
        #pragma unroll
        for (int l = 0; l < 2; l++) {
            int idx = tid + l*256;
            int r  = idx >> 2, kk = (idx & 3) * 4;
            float4 av = make_float4(0.f,0.f,0.f,0.f);
            if (row0 + r < M)
                av = *(const float4*)&A[(size_t)(row0 + r)*K + k0 + kk];
            As[kk+0][r] = av.x; As[kk+1][r] = av.y; As[kk+2][r] = av.z; As[kk+3][r] = av.w;
            int wr = idx >> 5, wc = (idx & 31) * 4;
            *(float4*)&Ws[wr][wc] = *(const float4*)&W[(size_t)(k0 + wr)*N + col0 + wc];
        }
        __syncthreads();
        #pragma unroll
        for (int k = 0; k < 16; k++) {
            float4 a0 = *(const float4*)&As[k][ty*4];
            float4 a1 = *(const float4*)&As[k][64 + ty*4];
            float4 b0 = *(const float4*)&Ws[k][tx*4];
            float4 b1 = *(const float4*)&Ws[k][64 + tx*4];
            float av[8] = {a0.x,a0.y,a0.z,a0.w, a1.x,a1.y,a1.z,a1.w};
            float bv[8] = {b0.x,b0.y,b0.z,b0.w, b1.x,b1.y,b1.z,b1.w};
            #pragma unroll
            for (int i = 0; i < 8; i++)
                #pragma unroll
                for (int j = 0; j < 8; j++)
                    acc[i][j] += av[i] * bv[j];
        }
    }
    #pragma unroll
    for (int i = 0; i < 8; i++) {
        int gr = row0 + ((i < 4) ? (ty*4 + i) : (64 + ty*4 + (i-4)));
        if (gr >= M) continue;
        #pragma unroll
        for (int j = 0; j < 8; j++) {
            int gc = col0 + ((j < 4) ? (tx*4 + j) : (64 + tx*4 + (j-4)));
            float v = acc[i][j] + bias[gc];
            if (EPI == 1) v = fmaxf(v, 0.f);
            if (EPI == 2) v += res[(size_t)gr*N + gc];
            C[(size_t)gr*N + gc] = v;
        }
    }
}

template<int EPI>
__global__ __launch_bounds__(256) void sgemm128(
    const float* __restrict__ A, const float* __restrict__ W,
    const float* __restrict__ bias, const float* __restrict__ res,
    float* __restrict__ C, int M, int N, int K)
{
    sgemm_body<EPI>(A, W, bias, res, C, M, N, K, blockIdx.y*128, blockIdx.x*128);
}

__global__ __launch_bounds__(256) void sgemm_qkv(
    const float* __restrict__ A,
    const float* __restrict__ W0, const float* __restrict__ W1, const float* __restrict__ W2,
    const float* __restrict__ b0, const float* __restrict__ b1, const float* __restrict__ b2,
    float* C0, float* C1, float* C2, int M, int N, int K)
{
    const float* W = (blockIdx.z == 0) ? W0 : (blockIdx.z == 1) ? W1 : W2;
    const float* bb = (blockIdx.z == 0) ? b0 : (blockIdx.z == 1) ? b1 : b2;
    float*       C = (blockIdx.z == 0) ? C0 : (blockIdx.z == 1) ? C1 : C2;
    sgemm_body<0>(A, W, bb, nullptr, C, M, N, K, blockIdx.y*128, blockIdx.x*128);
}

// ---------------- tiny N=8 projection: Y[row,h] = X[row,:]@Wp[:,h] + bp[h] ---
__global__ void proj8(const float* __restrict__ X, const float* __restrict__ Wp,
                      const float* __restrict__ bp, float* __restrict__ Y)
{
    int row = blockIdx.x;
    int tid = threadIdx.x;           // 256
    int h = tid & 7, seg = tid >> 3; // 32 segments x 16 k
    const float* x = X + (size_t)row*EE;
    float s = 0.f;
    #pragma unroll
    for (int k = 0; k < 16; k++) {
        int kk = seg*16 + k;
        s += x[kk] * Wp[kk*HH + h];
    }
    __shared__ float sm[256];
    sm[tid] = s;
    __syncthreads();
    if (tid < 8) {
        float acc = bp[tid];
        #pragma unroll
        for (int sg = 0; sg < 32; sg++) acc += sm[sg*8 + tid];
        Y[(size_t)row*HH + tid] = acc;
    }
}

// ---------------- P[m,h,r] = q_head(m,h) . krt_head(r,h) + t1[r,h], r<101 ----
__global__ __launch_bounds__(128) void pkernel(
    const float* __restrict__ q, const float* __restrict__ krt,
    const float* __restrict__ t1, float* __restrict__ P)
{
    int h = blockIdx.y;
    int m = blockIdx.x * 128 + threadIdx.x;
    float qr[64];
    const float4* qp = (const float4*)(q + (size_t)m*EE + h*DD);
    #pragma unroll
    for (int t = 0; t < 16; t++) {
        float4 v = qp[t];
        qr[t*4+0]=v.x; qr[t*4+1]=v.y; qr[t*4+2]=v.z; qr[t*4+3]=v.w;
    }
    float* Pp = P + ((size_t)m*HH + h)*RUSE;
    const float* kbase = krt + h*DD;
    for (int r = 0; r < RUSE; r++) {
        const float4* kp = (const float4*)(kbase + (size_t)r*EE);
        float acc = 0.f;
        #pragma unroll
        for (int t = 0; t < 16; t++) {
            float4 k4 = __ldg(&kp[t]);   // same addr across warp -> broadcast
            acc += qr[t*4+0]*k4.x + qr[t*4+1]*k4.y + qr[t*4+2]*k4.z + qr[t*4+3]*k4.w;
        }
        Pp[r] = acc + t1[r*HH + h];
    }
}

// ---------------- logits tile kernel: 64x64 tiles, causal-lower only --------
__global__ __launch_bounds__(256) void logits_kernel(
    const float* __restrict__ q, const float* __restrict__ ke,
    const float* __restrict__ P, const float* __restrict__ b0t,
    float* __restrict__ L)
{
    int jt = blockIdx.x, it = blockIdx.y;
    if (jt > it) return;
    int bh = blockIdx.z; int b = bh >> 3, h = bh & 7;
    __shared__ float Qs[64][68];   // [d][i]
    __shared__ float Ks[64][68];   // [d][j]
    int tid = threadIdx.x;
    int i0 = it*64, j0 = jt*64;
    #pragma unroll
    for (int l = 0; l < 4; l++) {
        int idx = tid + l*256;
        int r = idx >> 4, c4 = (idx & 15) << 2;
        float4 qv = *(const float4*)&q[((size_t)(b*SS + i0 + r))*EE + h*DD + c4];
        Qs[c4+0][r]=qv.x; Qs[c4+1][r]=qv.y; Qs[c4+2][r]=qv.z; Qs[c4+3][r]=qv.w;
        float4 kv4 = *(const float4*)&ke[((size_t)(b*SS + j0 + r))*EE + h*DD + c4];
        Ks[c4+0][r]=kv4.x; Ks[c4+1][r]=kv4.y; Ks[c4+2][r]=kv4.z; Ks[c4+3][r]=kv4.w;
    }
    __syncthreads();
    int tx = tid & 15, ty = tid >> 4;
    float acc[4][4] = {};
    #pragma unroll
    for (int d = 0; d < 64; d++) {
        float4 a  = *(const float4*)&Qs[d][ty*4];
        float4 bv = *(const float4*)&Ks[d][tx*4];
        float av[4] = {a.x, a.y, a.z, a.w};
        float bb2[4] = {bv.x, bv.y, bv.z, bv.w};
        #pragma unroll
        for (int i = 0; i < 4; i++)
            #pragma unroll
            for (int j = 0; j < 4; j++)
                acc[i][j] += av[i] * bb2[j];
    }
    #pragma unroll
    for (int i = 0; i < 4; i++) {
        int gi = i0 + ty*4 + i;
        const float* Pr = P + ((size_t)(b*SS + gi)*HH + h)*RUSE;
        #pragma unroll
        for (int j = 0; j < 4; j++) {
            int gj = j0 + tx*4 + j;
            float val;
            if (gj > gi) {
                val = -1e9f;
            } else {
                int off = gj - gi;                   // in [-511, 0]
                if (off < -100) off = -100;
                off += 100;                          // in [0, 100]
                val = acc[i][j]*0.125f + Pr[off] + b0t[(size_t)(b*SS + gj)*HH + h];
            }
            L[((size_t)bh*SS + gi)*SS + gj] = val;
        }
    }
}

// ---------------- softmax per (b,h,i) over j in [0, i] ----------------------
__global__ void softmax_kernel(float* __restrict__ L)
{
    int i = blockIdx.x;
    float* row = L + ((size_t)blockIdx.y*SS + i)*SS;
    int n = i + 1;
    int tid = threadIdx.x;  // 128
    float v[4];
    float mx = -1e30f;
    #pragma unroll
    for (int l = 0; l < 4; l++) {
        int j = tid + l*128;
        v[l] = (j < n) ? row[j] : -1e30f;
        mx = fmaxf(mx, v[l]);
    }
    #pragma unroll
    for (int o = 16; o > 0; o >>= 1) mx = fmaxf(mx, __shfl_xor_sync(0xffffffffu, mx, o));
    __shared__ float smx[4], ssum[4];
    if ((tid & 31) == 0) smx[tid>>5] = mx;
    __syncthreads();
    mx = fmaxf(fmaxf(smx[0], smx[1]), fmaxf(smx[2], smx[3]));
    float s = 0.f;
    #pragma unroll
    for (int l = 0; l < 4; l++) {
        int j = tid + l*128;
        if (j < n) { v[l] = __expf(v[l] - mx); s += v[l]; } else v[l] = 0.f;
    }
    #pragma unroll
    for (int o = 16; o > 0; o >>= 1) s += __shfl_xor_sync(0xffffffffu, s, o);
    if ((tid & 31) == 0) ssum[tid>>5] = s;
    __syncthreads();
    s = ssum[0] + ssum[1] + ssum[2] + ssum[3];
    float inv = 1.f / s;
    #pragma unroll
    for (int l = 0; l < 4; l++) {
        int j = tid + l*128;
        if (j < n) row[j] = v[l] * inv;
    }
}

// ---------------- att = scores @ kv_head, + residual -> v -------------------
__global__ __launch_bounds__(256) void att_kernel(
    const float* __restrict__ Sc, const float* __restrict__ kv,
    const float* __restrict__ vals, float* __restrict__ V)
{
    int it = blockIdx.x;
    int bh = blockIdx.y; int b = bh >> 3, h = bh & 7;
    int i0 = it*64;
    __shared__ float Ssm[64][68];  // [jj][i]
    __shared__ float Vsm[64][68];  // [jj][d]
    int tid = threadIdx.x, tx = tid & 15, ty = tid >> 4;
    float acc[4][4] = {};
    for (int jt = 0; jt <= it; jt++) {
        int j0 = jt*64;
        __syncthreads();
        #pragma unroll
        for (int l = 0; l < 4; l++) {
            int idx = tid + l*256;
            int r = idx >> 4, c4 = (idx & 15) << 2;
            int gi = i0 + r;
            float4 sv = *(const float4*)&Sc[((size_t)bh*SS + gi)*SS + j0 + c4];
            int gj = j0 + c4;
            if (gj + 0 > gi) sv.x = 0.f;
            if (gj + 1 > gi) sv.y = 0.f;
            if (gj + 2 > gi) sv.z = 0.f;
            if (gj + 3 > gi) sv.w = 0.f;
            Ssm[c4+0][r]=sv.x; Ssm[c4+1][r]=sv.y; Ssm[c4+2][r]=sv.z; Ssm[c4+3][r]=sv.w;
            float4 vv = *(const float4*)&kv[((size_t)(b*SS + j0 + r))*EE + h*DD + c4];
            *(float4*)&Vsm[r][c4] = vv;
        }
        __syncthreads();
        #pragma unroll
        for (int jj = 0; jj < 64; jj++) {
            float4 a  = *(const float4*)&Ssm[jj][ty*4];
            float4 bv = *(const float4*)&Vsm[jj][tx*4];
            float av[4] = {a.x, a.y, a.z, a.w};
            float bb2[4] = {bv.x, bv.y, bv.z, bv.w};
            #pragma unroll
            for (int i = 0; i < 4; i++)
                #pragma unroll
                for (int j = 0; j < 4; j++)
                    acc[i][j] += av[i] * bb2[j];
        }
    }
    #pragma unroll
    for (int i = 0; i < 4; i++) {
        int gi = i0 + ty*4 + i;
        size_t o = ((size_t)(b*SS + gi))*EE + h*DD + tx*4;
        float4 rv = *(const float4*)&vals[o];
        float4 ov = make_float4(acc[i][0]+rv.x, acc[i][1]+rv.y, acc[i][2]+rv.z, acc[i][3]+rv.w);
        *(float4*)&V[o] = ov;
    }
}

// ---------------- launch ----------------------------------------------------
extern "C" void kernel_launch(void* const* d_in, const int* in_sizes, int n_in,
                              void* d_out, int out_size)
{
    const float* values  = (const float*)d_in[0];
    // d_in[1] = values_mask (all-true by construction; causal mask suffices)
    const float* rel_enc = (const float*)d_in[2];
    const float* ln0_g   = (const float*)d_in[3];
    const float* ln0_b   = (const float*)d_in[4];
    const float* w_b0    = (const float*)d_in[5];
    const float* b_b0    = (const float*)d_in[6];
    const float* wq      = (const float*)d_in[7];
    const float* bq      = (const float*)d_in[8];
    const float* wke     = (const float*)d_in[9];
    const float* bke     = (const float*)d_in[10];
    const float* wkv     = (const float*)d_in[11];
    const float* bkv     = (const float*)d_in[12];
    const float* wkr     = (const float*)d_in[13];
    const float* bkr     = (const float*)d_in[14];
    const float* wab0    = (const float*)d_in[15];
    const float* bab0    = (const float*)d_in[16];
    const float* wab1    = (const float*)d_in[17];
    const float* bab1    = (const float*)d_in[18];
    const float* ln1_g   = (const float*)d_in[19];
    const float* ln1_b   = (const float*)d_in[20];
    const float* w11     = (const float*)d_in[21];
    const float* b11     = (const float*)d_in[22];
    const float* w12     = (const float*)d_in[23];
    const float* b12     = (const float*)d_in[24];
    float* out = (float*)d_out;

    float *p_xn,*p_x,*p_q,*p_ke,*p_kv,*p_krt,*p_t1,*p_b0t,*p_P,*p_L,*p_v,*p_vn,*p_h1;
    cudaGetSymbolAddress((void**)&p_xn,  g_xn);
    cudaGetSymbolAddress((void**)&p_x,   g_x);
    cudaGetSymbolAddress((void**)&p_q,   g_q);
    cudaGetSymbolAddress((void**)&p_ke,  g_ke);
    cudaGetSymbolAddress((void**)&p_kv,  g_kv);
    cudaGetSymbolAddress((void**)&p_krt, g_krt);
    cudaGetSymbolAddress((void**)&p_t1,  g_t1);
    cudaGetSymbolAddress((void**)&p_b0t, g_b0t);
    cudaGetSymbolAddress((void**)&p_P,   g_P);
    cudaGetSymbolAddress((void**)&p_L,   g_L);
    cudaGetSymbolAddress((void**)&p_v,   g_v);
    cudaGetSymbolAddress((void**)&p_vn,  g_vn);
    cudaGetSymbolAddress((void**)&p_h1,  g_h1);

    // 1) LN0
    ln_kernel<<<MR, 256>>>(values, ln0_g, ln0_b, p_xn);
    // 2) x = relu(xn @ w_b0 + b_b0)      (2048 x 2048, K=512)
    sgemm128<1><<<dim3(HIDD/128, MR/128), 256>>>(p_xn, w_b0, b_b0, nullptr, p_x, MR, HIDD, EE);
    // 3) q / ke / kv                      (2048 x 512, K=2048) fused via gridDim.z
    sgemm_qkv<<<dim3(EE/128, MR/128, 3), 256>>>(p_x, wq, wke, wkv, bq, bke, bkv,
                                                p_q, p_ke, p_kv, MR, EE, HIDD);
    // 4) kr_table = rel_enc @ wkr + bkr   (201 x 512, K=512)
    sgemm128<0><<<dim3(EE/128, 2), 256>>>(rel_enc, wkr, bkr, nullptr, p_krt, RFULL, EE, EE);
    // 5) t1 = kr_table @ wab1 + bab1      (201 x 8)
    proj8<<<RFULL, 256>>>(p_krt, wab1, bab1, p_t1);
    // 6) bias0 = ke @ wab0 + bab0         (2048 x 8)
    proj8<<<MR, 256>>>(p_ke, wab0, bab0, p_b0t);
    // 7) P[m,h,r] = q_head . krt_head + t1 (r in [0,100])
    pkernel<<<dim3(MR/128, HH), 128>>>(p_q, p_krt, p_t1, p_P);
    // 8) logits (causal-lower 64x64 tiles)
    logits_kernel<<<dim3(8, 8, BB*HH), 256>>>(p_q, p_ke, p_P, p_b0t, p_L);
    // 9) softmax per row
    softmax_kernel<<<dim3(SS, BB*HH), 128>>>(p_L);
    // 10) att @ kv + residual -> v
    att_kernel<<<dim3(8, BB*HH), 256>>>(p_L, p_kv, values, p_v);
    // 11) LN1
    ln_kernel<<<MR, 256>>>(p_v, ln1_g, ln1_b, p_vn);
    // 12) h1 = relu(vn @ w11 + b11)
    sgemm128<1><<<dim3(HIDD/128, MR/128), 256>>>(p_vn, w11, b11, nullptr, p_h1, MR, HIDD, EE);
    // 13) out = v + h1 @ w12 + b12
    sgemm128<2><<<dim3(EE/128, MR/128), 256>>>(p_h1, w12, b12, p_v, out, MR, EE, HIDD);
}

// round 4
// speedup vs baseline: 1.8164x; 1.8164x over previous
#include <cuda_runtime.h>
#include <cuda_bf16.h>
#include <cstdint>
#include <cstddef>

#define BB 4
#define SS 512
#define EE 512
#define HIDD 2048
#define HH 8
#define DD 64
#define RFULL 201
#define RUSE 101
#define MR (BB*SS)   // 2048

// ---------------- fp32 scratch ----------------------------------------------
__device__ __align__(128) float g_q [MR*EE];
__device__ __align__(128) float g_ke[MR*EE];
__device__ __align__(128) float g_kv[MR*EE];
__device__ __align__(128) float g_krt[RFULL*EE];
__device__ __align__(128) float g_t1[RFULL*HH];
__device__ __align__(128) float g_b0t[MR*HH];
__device__ __align__(128) float g_P[(size_t)MR*HH*RUSE];
__device__ __align__(128) float g_L[(size_t)BB*HH*SS*SS];
__device__ __align__(128) float g_v [MR*EE];

// ---------------- bf16 split scratch ----------------------------------------
__device__ __align__(128) __nv_bfloat16 g_xnh[MR*EE],   g_xnl[MR*EE];
__device__ __align__(128) __nv_bfloat16 g_xh [MR*HIDD], g_xl [MR*HIDD];
__device__ __align__(128) __nv_bfloat16 g_vnh[MR*EE],   g_vnl[MR*EE];
__device__ __align__(128) __nv_bfloat16 g_h1h[MR*HIDD], g_h1l[MR*HIDD];
__device__ __align__(128) __nv_bfloat16 g_reh[RFULL*EE + 64], g_rel_[RFULL*EE + 64];
// weights, transposed to [N][K] and split
__device__ __align__(128) __nv_bfloat16 g_wb0h[HIDD*EE], g_wb0l[HIDD*EE];
__device__ __align__(128) __nv_bfloat16 g_wqh [EE*HIDD], g_wql [EE*HIDD];
__device__ __align__(128) __nv_bfloat16 g_wkeh[EE*HIDD], g_wkel[EE*HIDD];
__device__ __align__(128) __nv_bfloat16 g_wkvh[EE*HIDD], g_wkvl[EE*HIDD];
__device__ __align__(128) __nv_bfloat16 g_wkrh[EE*EE],   g_wkrl[EE*EE];
__device__ __align__(128) __nv_bfloat16 g_w11h[HIDD*EE], g_w11l[HIDD*EE];
__device__ __align__(128) __nv_bfloat16 g_w12h[EE*HIDD], g_w12l[EE*HIDD];

// ---------------- PTX helpers (portable: sm_80-class PTX only) --------------
__device__ __forceinline__ uint32_t s2u(const void* p){
    uint32_t a;
    asm("{ .reg .u64 t; cvta.to.shared.u64 t, %1; cvt.u32.u64 %0, t; }" : "=r"(a) : "l"(p));
    return a;
}
__device__ __forceinline__ void cpa16(uint32_t dst, const void* src, uint32_t sz){
    asm volatile("cp.async.cg.shared.global [%0], [%1], 16, %2;" :: "r"(dst), "l"(src), "r"(sz));
}
__device__ __forceinline__ void cpcommit(){ asm volatile("cp.async.commit_group;" ::: "memory"); }
__device__ __forceinline__ void cpwait0(){ asm volatile("cp.async.wait_group 0;" ::: "memory"); }
__device__ __forceinline__ void cpwait1(){ asm volatile("cp.async.wait_group 1;" ::: "memory"); }

__device__ __forceinline__ void ldsm4(uint32_t* r, uint32_t addr){
    asm volatile("ldmatrix.sync.aligned.m8n8.x4.shared.b16 {%0,%1,%2,%3}, [%4];"
        : "=r"(r[0]), "=r"(r[1]), "=r"(r[2]), "=r"(r[3]) : "r"(addr));
}
__device__ __forceinline__ void mma16816(float* d, const uint32_t* a, const uint32_t* b){
    asm volatile("mma.sync.aligned.m16n8k16.row.col.f32.bf16.bf16.f32 "
        "{%0,%1,%2,%3}, {%4,%5,%6,%7}, {%8,%9}, {%0,%1,%2,%3};"
        : "+f"(d[0]), "+f"(d[1]), "+f"(d[2]), "+f"(d[3])
        : "r"(a[0]), "r"(a[1]), "r"(a[2]), "r"(a[3]), "r"(b[0]), "r"(b[1]));
}

// smem geometry: k-chunk 32, rows padded to 40 bf16 (80 B) -> conflict-free ldmatrix
#define KC 32
#define LDSM_STRIDE 40
#define TILE_B (128*LDSM_STRIDE*2)     // 10240
#define STAGE_B (4*TILE_B)             // 40960 (Ah, Al, Bh, Bl)
#define GSMEM_BYTES (2*STAGE_B)        // 81920

// ---------------- chunk loader ----------------------------------------------
__device__ __forceinline__ void load_chunk(uint32_t stage, int tid,
    const __nv_bfloat16* __restrict__ Ah, const __nv_bfloat16* __restrict__ Al,
    const __nv_bfloat16* __restrict__ Bh, const __nv_bfloat16* __restrict__ Bl,
    int m0, int n0, int k0, int M, int K)
{
    #pragma unroll
    for (int t = 0; t < 4; t++){
        const __nv_bfloat16* g = (t==0)?Ah:(t==1)?Al:(t==2)?Bh:Bl;
        int row0 = (t < 2) ? m0 : n0;
        uint32_t tb = stage + t*TILE_B;
        #pragma unroll
        for (int i = 0; i < 2; i++){
            int s = i*256 + tid;      // 0..511
            int r = s >> 2, seg = s & 3;
            uint32_t dst = tb + (uint32_t)(r*80 + seg*16);
            int gr = row0 + r;
            uint32_t sz = 16u;
            if (t < 2 && gr >= M){ sz = 0u; gr = M - 1; }
            cpa16(dst, (const char*)(g + (size_t)gr*K + k0) + seg*16, sz);
        }
    }
    cpcommit();
}

// ---------------- split-bf16 mma.sync GEMM ----------------------------------
// C[m][n] = sum_k A[m][k]*B[n][k]; EPI: 0 fp32+bias, 1 relu->bf16 hi/lo, 2 +bias+res
template<int EPI>
__device__ void gemm_body(
    const __nv_bfloat16* __restrict__ Ah, const __nv_bfloat16* __restrict__ Al,
    const __nv_bfloat16* __restrict__ Bh, const __nv_bfloat16* __restrict__ Bl,
    const float* __restrict__ bias, const float* __restrict__ res,
    float* __restrict__ Cf, __nv_bfloat16* __restrict__ Ch, __nv_bfloat16* __restrict__ Cl,
    int M, int N, int K)
{
    extern __shared__ char smem[];
    uint32_t sb = s2u(smem);
    int tid = threadIdx.x;
    int lane = tid & 31, warp = tid >> 5;
    int wm = warp >> 2;              // 0..1 -> 64 rows
    int wn = warp & 3;               // 0..3 -> 32 cols
    int m0 = blockIdx.y*128, n0 = blockIdx.x*128;

    // ldmatrix per-lane offsets
    int a_row  = wm*64 + (lane & 15);
    int a_col8 = (lane >> 4) * 8;
    int b_row  = wn*32 + (lane & 7) + ((lane & 16) ? 8 : 0);
    int b_col8 = ((lane & 8) ? 8 : 0);

    float acc[4][4][4];
    #pragma unroll
    for (int a = 0; a < 4; a++)
        #pragma unroll
        for (int b = 0; b < 4; b++)
            #pragma unroll
            for (int c = 0; c < 4; c++) acc[a][b][c] = 0.f;

    const int NC = K >> 5;
    uint32_t st0 = sb, st1 = sb + STAGE_B;

    load_chunk(st0, tid, Ah, Al, Bh, Bl, m0, n0, 0, M, K);

    for (int c = 0; c < NC; c++){
        uint32_t cur = (c & 1) ? st1 : st0;
        if (c + 1 < NC)
            load_chunk((c & 1) ? st0 : st1, tid, Ah, Al, Bh, Bl, m0, n0, (c+1)*KC, M, K);
        if (c + 1 < NC) cpwait1(); else cpwait0();
        __syncthreads();

        uint32_t cAh = cur, cAl = cur + TILE_B, cBh = cur + 2*TILE_B, cBl = cur + 3*TILE_B;
        #pragma unroll
        for (int ks = 0; ks < 2; ks++){
            int k0 = ks*16;
            uint32_t ah[4][4], al[4][4], bh[2][4], bl[2][4];
            #pragma unroll
            for (int mt = 0; mt < 4; mt++){
                uint32_t off = (uint32_t)(((a_row + mt*16)*LDSM_STRIDE) + k0 + a_col8) * 2u;
                ldsm4(ah[mt], cAh + off);
                ldsm4(al[mt], cAl + off);
            }
            #pragma unroll
            for (int p = 0; p < 2; p++){
                uint32_t off = (uint32_t)(((b_row + p*16)*LDSM_STRIDE) + k0 + b_col8) * 2u;
                ldsm4(bh[p], cBh + off);
                ldsm4(bl[p], cBl + off);
            }
            #pragma unroll
            for (int mt = 0; mt < 4; mt++)
                #pragma unroll
                for (int nt = 0; nt < 4; nt++){
                    const uint32_t* bhp = &bh[nt >> 1][(nt & 1)*2];
                    const uint32_t* blp = &bl[nt >> 1][(nt & 1)*2];
                    mma16816(acc[mt][nt], ah[mt], bhp);
                    mma16816(acc[mt][nt], ah[mt], blp);
                    mma16816(acc[mt][nt], al[mt], bhp);
                }
        }
        __syncthreads();
    }

    // epilogue
    int g = lane >> 2, tig = lane & 3;
    #pragma unroll
    for (int mt = 0; mt < 4; mt++){
        #pragma unroll
        for (int half = 0; half < 2; half++){
            int row = m0 + wm*64 + mt*16 + g + half*8;
            if (row >= M) continue;
            #pragma unroll
            for (int nt = 0; nt < 4; nt++){
                int col = n0 + wn*32 + nt*8 + tig*2;
                float c0 = acc[mt][nt][half*2 + 0];
                float c1 = acc[mt][nt][half*2 + 1];
                float v0 = c0 + bias[col];
                float v1 = c1 + bias[col + 1];
                size_t o = (size_t)row*N + col;
                if (EPI == 1){
                    v0 = fmaxf(v0, 0.f); v1 = fmaxf(v1, 0.f);
                    __nv_bfloat16 h0 = __float2bfloat16_rn(v0);
                    __nv_bfloat16 h1 = __float2bfloat16_rn(v1);
                    __nv_bfloat16 l0 = __float2bfloat16_rn(v0 - __bfloat162float(h0));
                    __nv_bfloat16 l1 = __float2bfloat16_rn(v1 - __bfloat162float(h1));
                    *(uint32_t*)((char*)Ch + o*2) =
                        (uint32_t)__bfloat16_as_ushort(h0) | ((uint32_t)__bfloat16_as_ushort(h1) << 16);
                    *(uint32_t*)((char*)Cl + o*2) =
                        (uint32_t)__bfloat16_as_ushort(l0) | ((uint32_t)__bfloat16_as_ushort(l1) << 16);
                } else {
                    if (EPI == 2){
                        float2 rv = *(const float2*)&res[o];
                        v0 += rv.x; v1 += rv.y;
                    }
                    *(float2*)&Cf[o] = make_float2(v0, v1);
                }
            }
        }
    }
}

template<int EPI>
__global__ __launch_bounds__(256, 1)
void gemm_tc(const __nv_bfloat16* Ah, const __nv_bfloat16* Al,
             const __nv_bfloat16* Bh, const __nv_bfloat16* Bl,
             const float* bias, const float* res,
             float* Cf, __nv_bfloat16* Ch, __nv_bfloat16* Cl, int M, int N, int K)
{
    gemm_body<EPI>(Ah, Al, Bh, Bl, bias, res, Cf, Ch, Cl, M, N, K);
}

__global__ __launch_bounds__(256, 1)
void gemm_qkv_tc(const __nv_bfloat16* Ah, const __nv_bfloat16* Al,
                 const __nv_bfloat16* B0h, const __nv_bfloat16* B0l,
                 const __nv_bfloat16* B1h, const __nv_bfloat16* B1l,
                 const __nv_bfloat16* B2h, const __nv_bfloat16* B2l,
                 const float* b0, const float* b1, const float* b2,
                 float* C0, float* C1, float* C2, int M, int N, int K)
{
    int z = blockIdx.z;
    const __nv_bfloat16* Bh = (z==0)?B0h:(z==1)?B1h:B2h;
    const __nv_bfloat16* Bl = (z==0)?B0l:(z==1)?B1l:B2l;
    const float* bias = (z==0)?b0:(z==1)?b1:b2;
    float* C = (z==0)?C0:(z==1)?C1:C2;
    gemm_body<0>(Ah, Al, Bh, Bl, bias, nullptr, C, nullptr, nullptr, M, N, K);
}

// ---------------- conversion kernels ----------------------------------------
__global__ void convA(const float* __restrict__ X, __nv_bfloat16* __restrict__ H,
                      __nv_bfloat16* __restrict__ L, int n)
{
    int i = blockIdx.x*256 + threadIdx.x;
    if (i < n){
        float x = X[i];
        __nv_bfloat16 h = __float2bfloat16_rn(x);
        H[i] = h;
        L[i] = __float2bfloat16_rn(x - __bfloat162float(h));
    }
}

// W [K][N] fp32 -> T [N][K] bf16 hi/lo
__global__ void convWT(const float* __restrict__ W, __nv_bfloat16* __restrict__ Th,
                       __nv_bfloat16* __restrict__ Tl, int K, int N)
{
    __shared__ float t[32][33];
    int bx = blockIdx.x*32;   // n
    int by = blockIdx.y*32;   // k
    int lx = threadIdx.x & 31, ly = threadIdx.x >> 5;
    #pragma unroll
    for (int i = 0; i < 32; i += 8)
        t[ly + i][lx] = W[(size_t)(by + ly + i)*N + bx + lx];
    __syncthreads();
    #pragma unroll
    for (int i = 0; i < 32; i += 8){
        int n = bx + ly + i, k = by + lx;
        float x = t[lx][ly + i];
        __nv_bfloat16 h = __float2bfloat16_rn(x);
        Th[(size_t)n*K + k] = h;
        Tl[(size_t)n*K + k] = __float2bfloat16_rn(x - __bfloat162float(h));
    }
}

// ---------------- LayerNorm -> bf16 hi/lo -----------------------------------
__global__ void ln_bf16(const float* __restrict__ X, const float* __restrict__ g,
                        const float* __restrict__ bt,
                        __nv_bfloat16* __restrict__ Yh, __nv_bfloat16* __restrict__ Yl)
{
    int row = blockIdx.x;
    int tid = threadIdx.x; // 256
    const float* x = X + (size_t)row*EE;
    float a = x[tid], c = x[tid + 256];
    float s  = a + c;
    float s2 = a*a + c*c;
    #pragma unroll
    for (int o = 16; o > 0; o >>= 1){
        s  += __shfl_xor_sync(0xffffffffu, s,  o);
        s2 += __shfl_xor_sync(0xffffffffu, s2, o);
    }
    __shared__ float sa[8], sbm[8];
    if ((tid & 31) == 0){ sa[tid>>5] = s; sbm[tid>>5] = s2; }
    __syncthreads();
    float ts = 0.f, ts2 = 0.f;
    #pragma unroll
    for (int w = 0; w < 8; w++){ ts += sa[w]; ts2 += sbm[w]; }
    float mean = ts * (1.f/512.f);
    float var  = ts2 * (1.f/512.f) - mean*mean;
    float r = rsqrtf(var + 1e-3f);
    float y0 = (a - mean)*r*g[tid]       + bt[tid];
    float y1 = (c - mean)*r*g[tid + 256] + bt[tid + 256];
    __nv_bfloat16 h0 = __float2bfloat16_rn(y0);
    __nv_bfloat16 h1 = __float2bfloat16_rn(y1);
    Yh[(size_t)row*EE + tid]       = h0;
    Yh[(size_t)row*EE + tid + 256] = h1;
    Yl[(size_t)row*EE + tid]       = __float2bfloat16_rn(y0 - __bfloat162float(h0));
    Yl[(size_t)row*EE + tid + 256] = __float2bfloat16_rn(y1 - __bfloat162float(h1));
}

// ---------------- tiny N=8 projection ---------------------------------------
__global__ void proj8(const float* __restrict__ X, const float* __restrict__ Wp,
                      const float* __restrict__ bp, float* __restrict__ Y)
{
    int row = blockIdx.x;
    int tid = threadIdx.x;
    int h = tid & 7, seg = tid >> 3;
    const float* x = X + (size_t)row*EE;
    float s = 0.f;
    #pragma unroll
    for (int k = 0; k < 16; k++){
        int kk = seg*16 + k;
        s += x[kk] * Wp[kk*HH + h];
    }
    __shared__ float sm[256];
    sm[tid] = s;
    __syncthreads();
    if (tid < 8){
        float acc = bp[tid];
        #pragma unroll
        for (int sg = 0; sg < 32; sg++) acc += sm[sg*8 + tid];
        Y[(size_t)row*HH + tid] = acc;
    }
}

// ---------------- P[m,h,r] --------------------------------------------------
__global__ __launch_bounds__(128) void pkernel(
    const float* __restrict__ q, const float* __restrict__ krt,
    const float* __restrict__ t1, float* __restrict__ P)
{
    int h = blockIdx.y;
    int m = blockIdx.x * 128 + threadIdx.x;
    float qr[64];
    const float4* qp = (const float4*)(q + (size_t)m*EE + h*DD);
    #pragma unroll
    for (int t = 0; t < 16; t++){
        float4 v = qp[t];
        qr[t*4+0]=v.x; qr[t*4+1]=v.y; qr[t*4+2]=v.z; qr[t*4+3]=v.w;
    }
    float* Pp = P + ((size_t)m*HH + h)*RUSE;
    const float* kbase = krt + h*DD;
    for (int r = 0; r < RUSE; r++){
        const float4* kp = (const float4*)(kbase + (size_t)r*EE);
        float acc = 0.f;
        #pragma unroll
        for (int t = 0; t < 16; t++){
            float4 k4 = __ldg(&kp[t]);
            acc += qr[t*4+0]*k4.x + qr[t*4+1]*k4.y + qr[t*4+2]*k4.z + qr[t*4+3]*k4.w;
        }
        Pp[r] = acc + t1[r*HH + h];
    }
}

// ---------------- logits ----------------------------------------------------
__global__ __launch_bounds__(256) void logits_kernel(
    const float* __restrict__ q, const float* __restrict__ ke,
    const float* __restrict__ P, const float* __restrict__ b0t,
    float* __restrict__ L)
{
    int jt = blockIdx.x, it = blockIdx.y;
    if (jt > it) return;
    int bh = blockIdx.z; int b = bh >> 3, h = bh & 7;
    __shared__ float Qs[64][68];
    __shared__ float Ks[64][68];
    int tid = threadIdx.x;
    int i0 = it*64, j0 = jt*64;
    #pragma unroll
    for (int l = 0; l < 4; l++){
        int idx = tid + l*256;
        int r = idx >> 4, c4 = (idx & 15) << 2;
        float4 qv = *(const float4*)&q[((size_t)(b*SS + i0 + r))*EE + h*DD + c4];
        Qs[c4+0][r]=qv.x; Qs[c4+1][r]=qv.y; Qs[c4+2][r]=qv.z; Qs[c4+3][r]=qv.w;
        float4 kv4 = *(const float4*)&ke[((size_t)(b*SS + j0 + r))*EE + h*DD + c4];
        Ks[c4+0][r]=kv4.x; Ks[c4+1][r]=kv4.y; Ks[c4+2][r]=kv4.z; Ks[c4+3][r]=kv4.w;
    }
    __syncthreads();
    int tx = tid & 15, ty = tid >> 4;
    float acc[4][4] = {};
    #pragma unroll
    for (int d = 0; d < 64; d++){
        float4 a  = *(const float4*)&Qs[d][ty*4];
        float4 bv = *(const float4*)&Ks[d][tx*4];
        float av[4] = {a.x, a.y, a.z, a.w};
        float bb2[4] = {bv.x, bv.y, bv.z, bv.w};
        #pragma unroll
        for (int i = 0; i < 4; i++)
            #pragma unroll
            for (int j = 0; j < 4; j++)
                acc[i][j] += av[i] * bb2[j];
    }
    #pragma unroll
    for (int i = 0; i < 4; i++){
        int gi = i0 + ty*4 + i;
        const float* Pr = P + ((size_t)(b*SS + gi)*HH + h)*RUSE;
        #pragma unroll
        for (int j = 0; j < 4; j++){
            int gj = j0 + tx*4 + j;
            float val;
            if (gj > gi){
                val = -1e9f;
            } else {
                int off = gj - gi;
                if (off < -100) off = -100;
                off += 100;
                val = acc[i][j]*0.125f + Pr[off] + b0t[(size_t)(b*SS + gj)*HH + h];
            }
            L[((size_t)bh*SS + gi)*SS + gj] = val;
        }
    }
}

// ---------------- softmax ---------------------------------------------------
__global__ void softmax_kernel(float* __restrict__ L)
{
    int i = blockIdx.x;
    float* row = L + ((size_t)blockIdx.y*SS + i)*SS;
    int n = i + 1;
    int tid = threadIdx.x;
    float v[4];
    float mx = -1e30f;
    #pragma unroll
    for (int l = 0; l < 4; l++){
        int j = tid + l*128;
        v[l] = (j < n) ? row[j] : -1e30f;
        mx = fmaxf(mx, v[l]);
    }
    #pragma unroll
    for (int o = 16; o > 0; o >>= 1) mx = fmaxf(mx, __shfl_xor_sync(0xffffffffu, mx, o));
    __shared__ float smx[4], ssum[4];
    if ((tid & 31) == 0) smx[tid>>5] = mx;
    __syncthreads();
    mx = fmaxf(fmaxf(smx[0], smx[1]), fmaxf(smx[2], smx[3]));
    float s = 0.f;
    #pragma unroll
    for (int l = 0; l < 4; l++){
        int j = tid + l*128;
        if (j < n){ v[l] = __expf(v[l] - mx); s += v[l]; } else v[l] = 0.f;
    }
    #pragma unroll
    for (int o = 16; o > 0; o >>= 1) s += __shfl_xor_sync(0xffffffffu, s, o);
    if ((tid & 31) == 0) ssum[tid>>5] = s;
    __syncthreads();
    s = ssum[0] + ssum[1] + ssum[2] + ssum[3];
    float inv = 1.f / s;
    #pragma unroll
    for (int l = 0; l < 4; l++){
        int j = tid + l*128;
        if (j < n) row[j] = v[l] * inv;
    }
}

// ---------------- att -------------------------------------------------------
__global__ __launch_bounds__(256) void att_kernel(
    const float* __restrict__ Sc, const float* __restrict__ kv,
    const float* __restrict__ vals, float* __restrict__ V)
{
    int it = blockIdx.x;
    int bh = blockIdx.y; int b = bh >> 3, h = bh & 7;
    int i0 = it*64;
    __shared__ float Ssm[64][68];
    __shared__ float Vsm[64][68];
    int tid = threadIdx.x, tx = tid & 15, ty = tid >> 4;
    float acc[4][4] = {};
    for (int jt = 0; jt <= it; jt++){
        int j0 = jt*64;
        __syncthreads();
        #pragma unroll
        for (int l = 0; l < 4; l++){
            int idx = tid + l*256;
            int r = idx >> 4, c4 = (idx & 15) << 2;
            int gi = i0 + r;
            float4 sv = *(const float4*)&Sc[((size_t)bh*SS + gi)*SS + j0 + c4];
            int gj = j0 + c4;
            if (gj + 0 > gi) sv.x = 0.f;
            if (gj + 1 > gi) sv.y = 0.f;
            if (gj + 2 > gi) sv.z = 0.f;
            if (gj + 3 > gi) sv.w = 0.f;
            Ssm[c4+0][r]=sv.x; Ssm[c4+1][r]=sv.y; Ssm[c4+2][r]=sv.z; Ssm[c4+3][r]=sv.w;
            float4 vv = *(const float4*)&kv[((size_t)(b*SS + j0 + r))*EE + h*DD + c4];
            *(float4*)&Vsm[r][c4] = vv;
        }
        __syncthreads();
        #pragma unroll
        for (int jj = 0; jj < 64; jj++){
            float4 a  = *(const float4*)&Ssm[jj][ty*4];
            float4 bv = *(const float4*)&Vsm[jj][tx*4];
            float av[4] = {a.x, a.y, a.z, a.w};
            float bb2[4] = {bv.x, bv.y, bv.z, bv.w};
            #pragma unroll
            for (int i = 0; i < 4; i++)
                #pragma unroll
                for (int j = 0; j < 4; j++)
                    acc[i][j] += av[i] * bb2[j];
        }
    }
    #pragma unroll
    for (int i = 0; i < 4; i++){
        int gi = i0 + ty*4 + i;
        size_t o = ((size_t)(b*SS + gi))*EE + h*DD + tx*4;
        float4 rv = *(const float4*)&vals[o];
        float4 ov = make_float4(acc[i][0]+rv.x, acc[i][1]+rv.y, acc[i][2]+rv.z, acc[i][3]+rv.w);
        *(float4*)&V[o] = ov;
    }
}

// ---------------- launch ----------------------------------------------------
extern "C" void kernel_launch(void* const* d_in, const int* in_sizes, int n_in,
                              void* d_out, int out_size)
{
    const float* values  = (const float*)d_in[0];
    const float* rel_enc = (const float*)d_in[2];
    const float* ln0_g   = (const float*)d_in[3];
    const float* ln0_b   = (const float*)d_in[4];
    const float* w_b0    = (const float*)d_in[5];
    const float* b_b0    = (const float*)d_in[6];
    const float* wq      = (const float*)d_in[7];
    const float* bq      = (const float*)d_in[8];
    const float* wke     = (const float*)d_in[9];
    const float* bke     = (const float*)d_in[10];
    const float* wkv     = (const float*)d_in[11];
    const float* bkv     = (const float*)d_in[12];
    const float* wkr     = (const float*)d_in[13];
    const float* bkr     = (const float*)d_in[14];
    const float* wab0    = (const float*)d_in[15];
    const float* bab0    = (const float*)d_in[16];
    const float* wab1    = (const float*)d_in[17];
    const float* bab1    = (const float*)d_in[18];
    const float* ln1_g   = (const float*)d_in[19];
    const float* ln1_b   = (const float*)d_in[20];
    const float* w11     = (const float*)d_in[21];
    const float* b11     = (const float*)d_in[22];
    const float* w12     = (const float*)d_in[23];
    const float* b12     = (const float*)d_in[24];
    float* out = (float*)d_out;

    float *p_q,*p_ke,*p_kv,*p_krt,*p_t1,*p_b0t,*p_P,*p_L,*p_v;
    cudaGetSymbolAddress((void**)&p_q,   g_q);
    cudaGetSymbolAddress((void**)&p_ke,  g_ke);
    cudaGetSymbolAddress((void**)&p_kv,  g_kv);
    cudaGetSymbolAddress((void**)&p_krt, g_krt);
    cudaGetSymbolAddress((void**)&p_t1,  g_t1);
    cudaGetSymbolAddress((void**)&p_b0t, g_b0t);
    cudaGetSymbolAddress((void**)&p_P,   g_P);
    cudaGetSymbolAddress((void**)&p_L,   g_L);
    cudaGetSymbolAddress((void**)&p_v,   g_v);

    __nv_bfloat16 *xnh,*xnl,*xh,*xl,*vnh,*vnl,*h1h,*h1l,*reh,*rel;
    __nv_bfloat16 *wb0h,*wb0l,*wqh,*wql,*wkeh,*wkel,*wkvh,*wkvl,*wkrh,*wkrl,*w11h,*w11l,*w12h,*w12l;
    cudaGetSymbolAddress((void**)&xnh, g_xnh); cudaGetSymbolAddress((void**)&xnl, g_xnl);
    cudaGetSymbolAddress((void**)&xh,  g_xh);  cudaGetSymbolAddress((void**)&xl,  g_xl);
    cudaGetSymbolAddress((void**)&vnh, g_vnh); cudaGetSymbolAddress((void**)&vnl, g_vnl);
    cudaGetSymbolAddress((void**)&h1h, g_h1h); cudaGetSymbolAddress((void**)&h1l, g_h1l);
    cudaGetSymbolAddress((void**)&reh, g_reh); cudaGetSymbolAddress((void**)&rel, g_rel_);
    cudaGetSymbolAddress((void**)&wb0h, g_wb0h); cudaGetSymbolAddress((void**)&wb0l, g_wb0l);
    cudaGetSymbolAddress((void**)&wqh,  g_wqh);  cudaGetSymbolAddress((void**)&wql,  g_wql);
    cudaGetSymbolAddress((void**)&wkeh, g_wkeh); cudaGetSymbolAddress((void**)&wkel, g_wkel);
    cudaGetSymbolAddress((void**)&wkvh, g_wkvh); cudaGetSymbolAddress((void**)&wkvl, g_wkvl);
    cudaGetSymbolAddress((void**)&wkrh, g_wkrh); cudaGetSymbolAddress((void**)&wkrl, g_wkrl);
    cudaGetSymbolAddress((void**)&w11h, g_w11h); cudaGetSymbolAddress((void**)&w11l, g_w11l);
    cudaGetSymbolAddress((void**)&w12h, g_w12h); cudaGetSymbolAddress((void**)&w12l, g_w12l);

    cudaFuncSetAttribute(gemm_tc<0>,  cudaFuncAttributeMaxDynamicSharedMemorySize, GSMEM_BYTES);
    cudaFuncSetAttribute(gemm_tc<1>,  cudaFuncAttributeMaxDynamicSharedMemorySize, GSMEM_BYTES);
    cudaFuncSetAttribute(gemm_tc<2>,  cudaFuncAttributeMaxDynamicSharedMemorySize, GSMEM_BYTES);
    cudaFuncSetAttribute(gemm_qkv_tc, cudaFuncAttributeMaxDynamicSharedMemorySize, GSMEM_BYTES);

    // weight conversion + transpose (W[K][N] -> T[N][K] hi/lo)
    convWT<<<dim3(HIDD/32, EE/32),   256>>>(w_b0, wb0h, wb0l, EE,   HIDD);
    convWT<<<dim3(EE/32,   HIDD/32), 256>>>(wq,   wqh,  wql,  HIDD, EE);
    convWT<<<dim3(EE/32,   HIDD/32), 256>>>(wke,  wkeh, wkel, HIDD, EE);
    convWT<<<dim3(EE/32,   HIDD/32), 256>>>(wkv,  wkvh, wkvl, HIDD, EE);
    convWT<<<dim3(EE/32,   EE/32),   256>>>(wkr,  wkrh, wkrl, EE,   EE);
    convWT<<<dim3(HIDD/32, EE/32),   256>>>(w11,  w11h, w11l, EE,   HIDD);
    convWT<<<dim3(EE/32,   HIDD/32), 256>>>(w12,  w12h, w12l, HIDD, EE);
    convA<<<(RFULL*EE + 255)/256, 256>>>(rel_enc, reh, rel, RFULL*EE);

    // 1) LN0 -> bf16 hi/lo
    ln_bf16<<<MR, 256>>>(values, ln0_g, ln0_b, xnh, xnl);
    // 2) x = relu(xn @ w_b0 + b_b0) -> bf16 hi/lo
    gemm_tc<1><<<dim3(HIDD/128, MR/128), 256, GSMEM_BYTES>>>(
        xnh, xnl, wb0h, wb0l, b_b0, nullptr, nullptr, xh, xl, MR, HIDD, EE);
    // 3) q / ke / kv (fp32 out)
    gemm_qkv_tc<<<dim3(EE/128, MR/128, 3), 256, GSMEM_BYTES>>>(
        xh, xl, wqh, wql, wkeh, wkel, wkvh, wkvl, bq, bke, bkv,
        p_q, p_ke, p_kv, MR, EE, HIDD);
    // 4) kr_table = rel_enc @ wkr + bkr  (M=201)
    gemm_tc<0><<<dim3(EE/128, 2), 256, GSMEM_BYTES>>>(
        reh, rel, wkrh, wkrl, bkr, nullptr, p_krt, nullptr, nullptr, RFULL, EE, EE);
    // 5) t1 / bias0
    proj8<<<RFULL, 256>>>(p_krt, wab1, bab1, p_t1);
    proj8<<<MR, 256>>>(p_ke, wab0, bab0, p_b0t);
    // 7) P
    pkernel<<<dim3(MR/128, HH), 128>>>(p_q, p_krt, p_t1, p_P);
    // 8) logits
    logits_kernel<<<dim3(8, 8, BB*HH), 256>>>(p_q, p_ke, p_P, p_b0t, p_L);
    // 9) softmax
    softmax_kernel<<<dim3(SS, BB*HH), 128>>>(p_L);
    // 10) att + residual
    att_kernel<<<dim3(8, BB*HH), 256>>>(p_L, p_kv, values, p_v);
    // 11) LN1 -> bf16
    ln_bf16<<<MR, 256>>>(p_v, ln1_g, ln1_b, vnh, vnl);
    // 12) h1 = relu(vn @ w11 + b11) -> bf16
    gemm_tc<1><<<dim3(HIDD/128, MR/128), 256, GSMEM_BYTES>>>(
        vnh, vnl, w11h, w11l, b11, nullptr, nullptr, h1h, h1l, MR, HIDD, EE);
    // 13) out = v + h1 @ w12 + b12
    gemm_tc<2><<<dim3(EE/128, MR/128), 256, GSMEM_BYTES>>>(
        h1h, h1l, w12h, w12l, b12, p_v, out, nullptr, nullptr, MR, EE, HIDD);
}

// round 5
// speedup vs baseline: 1.9072x; 1.0500x over previous
#include <cuda_runtime.h>
#include <cuda_bf16.h>
#include <cstdint>
#include <cstddef>

#define BB 4
#define SS 512
#define EE 512
#define HIDD 2048
#define HH 8
#define DD 64
#define RFULL 201
#define RUSE 101
#define MR (BB*SS)   // 2048

// ---------------- fp32 scratch ----------------------------------------------
__device__ __align__(128) float g_q [MR*EE];
__device__ __align__(128) float g_ke[MR*EE];
__device__ __align__(128) float g_kv[MR*EE];
__device__ __align__(128) float g_krt[RFULL*EE];
__device__ __align__(128) float g_t1[RFULL*HH];
__device__ __align__(128) float g_b0t[MR*HH];
__device__ __align__(128) float g_P[(size_t)MR*HH*RUSE];
__device__ __align__(128) float g_L[(size_t)BB*HH*SS*SS];
__device__ __align__(128) float g_v [MR*EE];

// ---------------- bf16 split scratch ----------------------------------------
__device__ __align__(128) __nv_bfloat16 g_xnh[MR*EE],   g_xnl[MR*EE];
__device__ __align__(128) __nv_bfloat16 g_xh [MR*HIDD], g_xl [MR*HIDD];
__device__ __align__(128) __nv_bfloat16 g_vnh[MR*EE],   g_vnl[MR*EE];
__device__ __align__(128) __nv_bfloat16 g_h1h[MR*HIDD], g_h1l[MR*HIDD];
__device__ __align__(128) __nv_bfloat16 g_reh[RFULL*EE + 64], g_rel_[RFULL*EE + 64];
// weights, transposed to [N][K] and split
__device__ __align__(128) __nv_bfloat16 g_wb0h[HIDD*EE], g_wb0l[HIDD*EE];
__device__ __align__(128) __nv_bfloat16 g_wqh [EE*HIDD], g_wql [EE*HIDD];
__device__ __align__(128) __nv_bfloat16 g_wkeh[EE*HIDD], g_wkel[EE*HIDD];
__device__ __align__(128) __nv_bfloat16 g_wkvh[EE*HIDD], g_wkvl[EE*HIDD];
__device__ __align__(128) __nv_bfloat16 g_wkrh[EE*EE],   g_wkrl[EE*EE];
__device__ __align__(128) __nv_bfloat16 g_w11h[HIDD*EE], g_w11l[HIDD*EE];
__device__ __align__(128) __nv_bfloat16 g_w12h[EE*HIDD], g_w12l[EE*HIDD];

// ---------------- PTX helpers (portable sm_80-class PTX only) ---------------
__device__ __forceinline__ uint32_t s2u(const void* p){
    uint32_t a;
    asm("{ .reg .u64 t; cvta.to.shared.u64 t, %1; cvt.u32.u64 %0, t; }" : "=r"(a) : "l"(p));
    return a;
}
__device__ __forceinline__ void cpa16(uint32_t dst, const void* src, uint32_t sz){
    asm volatile("cp.async.cg.shared.global [%0], [%1], 16, %2;" :: "r"(dst), "l"(src), "r"(sz));
}
__device__ __forceinline__ void cpcommit(){ asm volatile("cp.async.commit_group;" ::: "memory"); }
__device__ __forceinline__ void cpwait0(){ asm volatile("cp.async.wait_group 0;" ::: "memory"); }
__device__ __forceinline__ void cpwait1(){ asm volatile("cp.async.wait_group 1;" ::: "memory"); }

__device__ __forceinline__ void ldsm4(uint32_t* r, uint32_t addr){
    asm volatile("ldmatrix.sync.aligned.m8n8.x4.shared.b16 {%0,%1,%2,%3}, [%4];"
        : "=r"(r[0]), "=r"(r[1]), "=r"(r[2]), "=r"(r[3]) : "r"(addr));
}
__device__ __forceinline__ void mma16816(float* d, const uint32_t* a, const uint32_t* b){
    asm volatile("mma.sync.aligned.m16n8k16.row.col.f32.bf16.bf16.f32 "
        "{%0,%1,%2,%3}, {%4,%5,%6,%7}, {%8,%9}, {%0,%1,%2,%3};"
        : "+f"(d[0]), "+f"(d[1]), "+f"(d[2]), "+f"(d[3])
        : "r"(a[0]), "r"(a[1]), "r"(a[2]), "r"(a[3]), "r"(b[0]), "r"(b[1]));
}

// shared geometry: k-chunk 32, rows padded to 40 bf16 (80 B)
#define KC 32
#define LDSM_STRIDE 40
#define TILE_B (128*LDSM_STRIDE*2)       // 10240 (128-row tile)
#define STAGE_B (4*TILE_B)               // 40960
#define GSMEM_BYTES (2*STAGE_B)          // 81920  (128x128 kernel)

#define TILE_A2 (128*LDSM_STRIDE*2)      // 10240
#define TILE_B2 (256*LDSM_STRIDE*2)      // 20480
#define STAGE_B2 (2*TILE_A2 + 2*TILE_B2) // 61440
#define GSMEM2_BYTES (2*STAGE_B2)        // 122880 (128x256 kernel)

// ---------------- chunk loader (128x128) ------------------------------------
__device__ __forceinline__ void load_chunk(uint32_t stage, int tid,
    const __nv_bfloat16* __restrict__ Ah, const __nv_bfloat16* __restrict__ Al,
    const __nv_bfloat16* __restrict__ Bh, const __nv_bfloat16* __restrict__ Bl,
    int m0, int n0, int k0, int M, int K)
{
    #pragma unroll
    for (int t = 0; t < 4; t++){
        const __nv_bfloat16* g = (t==0)?Ah:(t==1)?Al:(t==2)?Bh:Bl;
        int row0 = (t < 2) ? m0 : n0;
        uint32_t tb = stage + t*TILE_B;
        #pragma unroll
        for (int i = 0; i < 2; i++){
            int s = i*256 + tid;
            int r = s >> 2, seg = s & 3;
            uint32_t dst = tb + (uint32_t)(r*80 + seg*16);
            int gr = row0 + r;
            uint32_t sz = 16u;
            if (t < 2 && gr >= M){ sz = 0u; gr = M - 1; }
            cpa16(dst, (const char*)(g + (size_t)gr*K + k0) + seg*16, sz);
        }
    }
    cpcommit();
}

// ---------------- chunk loader (128x256) ------------------------------------
__device__ __forceinline__ void load_chunk_big(uint32_t stage, int tid,
    const __nv_bfloat16* __restrict__ Ah, const __nv_bfloat16* __restrict__ Al,
    const __nv_bfloat16* __restrict__ Bh, const __nv_bfloat16* __restrict__ Bl,
    int m0, int n0, int k0, int M, int K)
{
    #pragma unroll
    for (int t = 0; t < 2; t++){
        const __nv_bfloat16* g = t ? Al : Ah;
        uint32_t tb = stage + t*TILE_A2;
        #pragma unroll
        for (int i = 0; i < 2; i++){
            int s = i*256 + tid;
            int r = s >> 2, seg = s & 3;
            int gr = m0 + r;
            uint32_t sz = 16u;
            if (gr >= M){ sz = 0u; gr = M - 1; }
            cpa16(tb + (uint32_t)(r*80 + seg*16),
                  (const char*)(g + (size_t)gr*K + k0) + seg*16, sz);
        }
    }
    #pragma unroll
    for (int t = 0; t < 2; t++){
        const __nv_bfloat16* g = t ? Bl : Bh;
        uint32_t tb = stage + 2*TILE_A2 + t*TILE_B2;
        #pragma unroll
        for (int i = 0; i < 4; i++){
            int s = i*256 + tid;
            int r = s >> 2, seg = s & 3;
            cpa16(tb + (uint32_t)(r*80 + seg*16),
                  (const char*)(g + (size_t)(n0 + r)*K + k0) + seg*16, 16u);
        }
    }
    cpcommit();
}

// ---------------- 128x128 split-bf16 GEMM -----------------------------------
// EPI: 0 fp32+bias, 1 relu->bf16 hi/lo, 2 +bias+res fp32
template<int EPI>
__device__ void gemm_body(
    const __nv_bfloat16* __restrict__ Ah, const __nv_bfloat16* __restrict__ Al,
    const __nv_bfloat16* __restrict__ Bh, const __nv_bfloat16* __restrict__ Bl,
    const float* __restrict__ bias, const float* __restrict__ res,
    float* __restrict__ Cf, __nv_bfloat16* __restrict__ Ch, __nv_bfloat16* __restrict__ Cl,
    int M, int N, int K)
{
    extern __shared__ char smem[];
    uint32_t sb = s2u(smem);
    int tid = threadIdx.x;
    int lane = tid & 31, warp = tid >> 5;
    int wm = warp >> 2, wn = warp & 3;
    int m0 = blockIdx.y*128, n0 = blockIdx.x*128;

    int a_row  = wm*64 + (lane & 15);
    int a_col8 = (lane >> 4) * 8;
    int b_row  = wn*32 + (lane & 7) + ((lane & 16) ? 8 : 0);
    int b_col8 = ((lane & 8) ? 8 : 0);

    float acc[4][4][4];
    #pragma unroll
    for (int a = 0; a < 4; a++)
        #pragma unroll
        for (int b = 0; b < 4; b++)
            #pragma unroll
            for (int c = 0; c < 4; c++) acc[a][b][c] = 0.f;

    const int NC = K >> 5;
    uint32_t st0 = sb, st1 = sb + STAGE_B;

    load_chunk(st0, tid, Ah, Al, Bh, Bl, m0, n0, 0, M, K);

    for (int c = 0; c < NC; c++){
        uint32_t cur = (c & 1) ? st1 : st0;
        if (c + 1 < NC)
            load_chunk((c & 1) ? st0 : st1, tid, Ah, Al, Bh, Bl, m0, n0, (c+1)*KC, M, K);
        if (c + 1 < NC) cpwait1(); else cpwait0();
        __syncthreads();

        uint32_t cAh = cur, cAl = cur + TILE_B, cBh = cur + 2*TILE_B, cBl = cur + 3*TILE_B;
        #pragma unroll
        for (int ks = 0; ks < 2; ks++){
            int k0 = ks*16;
            uint32_t ah[4][4], al[4][4], bh[2][4], bl[2][4];
            #pragma unroll
            for (int mt = 0; mt < 4; mt++){
                uint32_t off = (uint32_t)(((a_row + mt*16)*LDSM_STRIDE) + k0 + a_col8) * 2u;
                ldsm4(ah[mt], cAh + off);
                ldsm4(al[mt], cAl + off);
            }
            #pragma unroll
            for (int p = 0; p < 2; p++){
                uint32_t off = (uint32_t)(((b_row + p*16)*LDSM_STRIDE) + k0 + b_col8) * 2u;
                ldsm4(bh[p], cBh + off);
                ldsm4(bl[p], cBl + off);
            }
            #pragma unroll
            for (int mt = 0; mt < 4; mt++)
                #pragma unroll
                for (int nt = 0; nt < 4; nt++){
                    const uint32_t* bhp = &bh[nt >> 1][(nt & 1)*2];
                    const uint32_t* blp = &bl[nt >> 1][(nt & 1)*2];
                    mma16816(acc[mt][nt], ah[mt], bhp);
                    mma16816(acc[mt][nt], ah[mt], blp);
                    mma16816(acc[mt][nt], al[mt], bhp);
                }
        }
        __syncthreads();
    }

    int g = lane >> 2, tig = lane & 3;
    #pragma unroll
    for (int mt = 0; mt < 4; mt++){
        #pragma unroll
        for (int half = 0; half < 2; half++){
            int row = m0 + wm*64 + mt*16 + g + half*8;
            if (row >= M) continue;
            #pragma unroll
            for (int nt = 0; nt < 4; nt++){
                int col = n0 + wn*32 + nt*8 + tig*2;
                float v0 = acc[mt][nt][half*2 + 0] + bias[col];
                float v1 = acc[mt][nt][half*2 + 1] + bias[col + 1];
                size_t o = (size_t)row*N + col;
                if (EPI == 1){
                    v0 = fmaxf(v0, 0.f); v1 = fmaxf(v1, 0.f);
                    __nv_bfloat16 h0 = __float2bfloat16_rn(v0);
                    __nv_bfloat16 h1 = __float2bfloat16_rn(v1);
                    __nv_bfloat16 l0 = __float2bfloat16_rn(v0 - __bfloat162float(h0));
                    __nv_bfloat16 l1 = __float2bfloat16_rn(v1 - __bfloat162float(h1));
                    *(uint32_t*)((char*)Ch + o*2) =
                        (uint32_t)__bfloat16_as_ushort(h0) | ((uint32_t)__bfloat16_as_ushort(h1) << 16);
                    *(uint32_t*)((char*)Cl + o*2) =
                        (uint32_t)__bfloat16_as_ushort(l0) | ((uint32_t)__bfloat16_as_ushort(l1) << 16);
                } else {
                    if (EPI == 2){
                        float2 rv = *(const float2*)&res[o];
                        v0 += rv.x; v1 += rv.y;
                    }
                    *(float2*)&Cf[o] = make_float2(v0, v1);
                }
            }
        }
    }
}

template<int EPI>
__global__ __launch_bounds__(256, 1)
void gemm_tc(const __nv_bfloat16* Ah, const __nv_bfloat16* Al,
             const __nv_bfloat16* Bh, const __nv_bfloat16* Bl,
             const float* bias, const float* res,
             float* Cf, __nv_bfloat16* Ch, __nv_bfloat16* Cl, int M, int N, int K)
{
    gemm_body<EPI>(Ah, Al, Bh, Bl, bias, res, Cf, Ch, Cl, M, N, K);
}

__global__ __launch_bounds__(256, 1)
void gemm_qkv_tc(const __nv_bfloat16* Ah, const __nv_bfloat16* Al,
                 const __nv_bfloat16* B0h, const __nv_bfloat16* B0l,
                 const __nv_bfloat16* B1h, const __nv_bfloat16* B1l,
                 const __nv_bfloat16* B2h, const __nv_bfloat16* B2l,
                 const float* b0, const float* b1, const float* b2,
                 float* C0, float* C1, float* C2, int M, int N, int K)
{
    int z = blockIdx.z;
    const __nv_bfloat16* Bh = (z==0)?B0h:(z==1)?B1h:B2h;
    const __nv_bfloat16* Bl = (z==0)?B0l:(z==1)?B1l:B2l;
    const float* bias = (z==0)?b0:(z==1)?b1:b2;
    float* C = (z==0)?C0:(z==1)?C1:C2;
    gemm_body<0>(Ah, Al, Bh, Bl, bias, nullptr, C, nullptr, nullptr, M, N, K);
}

// ---------------- 128x256 split-bf16 GEMM, relu -> bf16 hi/lo ---------------
__global__ __launch_bounds__(256, 1)
void gemm_big_relu(const __nv_bfloat16* __restrict__ Ah, const __nv_bfloat16* __restrict__ Al,
                   const __nv_bfloat16* __restrict__ Bh, const __nv_bfloat16* __restrict__ Bl,
                   const float* __restrict__ bias,
                   __nv_bfloat16* __restrict__ Ch, __nv_bfloat16* __restrict__ Cl,
                   int M, int N, int K)
{
    extern __shared__ char smem[];
    uint32_t sb = s2u(smem);
    int tid = threadIdx.x;
    int lane = tid & 31, warp = tid >> 5;
    int wm = warp >> 2;              // 0..1 -> 64 rows
    int wn = warp & 3;               // 0..3 -> 64 cols
    int m0 = blockIdx.y*128, n0 = blockIdx.x*256;

    int a_row  = wm*64 + (lane & 15);
    int a_col8 = (lane >> 4) * 8;
    int b_rowb = wn*64 + (lane & 7) + ((lane & 16) ? 8 : 0);
    int b_col8 = ((lane & 8) ? 8 : 0);

    float acc[4][8][4];
    #pragma unroll
    for (int a = 0; a < 4; a++)
        #pragma unroll
        for (int b = 0; b < 8; b++)
            #pragma unroll
            for (int c = 0; c < 4; c++) acc[a][b][c] = 0.f;

    const int NC = K >> 5;
    uint32_t st0 = sb, st1 = sb + STAGE_B2;

    load_chunk_big(st0, tid, Ah, Al, Bh, Bl, m0, n0, 0, M, K);

    for (int c = 0; c < NC; c++){
        uint32_t cur = (c & 1) ? st1 : st0;
        if (c + 1 < NC)
            load_chunk_big((c & 1) ? st0 : st1, tid, Ah, Al, Bh, Bl, m0, n0, (c+1)*KC, M, K);
        if (c + 1 < NC) cpwait1(); else cpwait0();
        __syncthreads();

        uint32_t cAh = cur, cAl = cur + TILE_A2;
        uint32_t cBh = cur + 2*TILE_A2, cBl = cur + 2*TILE_A2 + TILE_B2;
        #pragma unroll
        for (int ks = 0; ks < 2; ks++){
            int k0 = ks*16;
            uint32_t ah[4][4], al[4][4];
            #pragma unroll
            for (int mt = 0; mt < 4; mt++){
                uint32_t off = (uint32_t)(((a_row + mt*16)*LDSM_STRIDE) + k0 + a_col8) * 2u;
                ldsm4(ah[mt], cAh + off);
                ldsm4(al[mt], cAl + off);
            }
            #pragma unroll
            for (int h2 = 0; h2 < 2; h2++){
                uint32_t bh[2][4], bl[2][4];
                #pragma unroll
                for (int p = 0; p < 2; p++){
                    uint32_t off = (uint32_t)(((b_rowb + (h2*2 + p)*16)*LDSM_STRIDE) + k0 + b_col8) * 2u;
                    ldsm4(bh[p], cBh + off);
                    ldsm4(bl[p], cBl + off);
                }
                #pragma unroll
                for (int mt = 0; mt < 4; mt++)
                    #pragma unroll
                    for (int j = 0; j < 4; j++){
                        const uint32_t* bhp = &bh[j >> 1][(j & 1)*2];
                        const uint32_t* blp = &bl[j >> 1][(j & 1)*2];
                        float* a4 = acc[mt][h2*4 + j];
                        mma16816(a4, ah[mt], bhp);
                        mma16816(a4, ah[mt], blp);
                        mma16816(a4, al[mt], bhp);
                    }
            }
        }
        __syncthreads();
    }

    int g = lane >> 2, tig = lane & 3;
    #pragma unroll
    for (int mt = 0; mt < 4; mt++){
        #pragma unroll
        for (int half = 0; half < 2; half++){
            int row = m0 + wm*64 + mt*16 + g + half*8;
            if (row >= M) continue;
            #pragma unroll
            for (int nt8 = 0; nt8 < 8; nt8++){
                int col = n0 + wn*64 + nt8*8 + tig*2;
                float v0 = fmaxf(acc[mt][nt8][half*2 + 0] + bias[col],     0.f);
                float v1 = fmaxf(acc[mt][nt8][half*2 + 1] + bias[col + 1], 0.f);
                size_t o = (size_t)row*N + col;
                __nv_bfloat16 h0 = __float2bfloat16_rn(v0);
                __nv_bfloat16 h1 = __float2bfloat16_rn(v1);
                __nv_bfloat16 l0 = __float2bfloat16_rn(v0 - __bfloat162float(h0));
                __nv_bfloat16 l1 = __float2bfloat16_rn(v1 - __bfloat162float(h1));
                *(uint32_t*)((char*)Ch + o*2) =
                    (uint32_t)__bfloat16_as_ushort(h0) | ((uint32_t)__bfloat16_as_ushort(h1) << 16);
                *(uint32_t*)((char*)Cl + o*2) =
                    (uint32_t)__bfloat16_as_ushort(l0) | ((uint32_t)__bfloat16_as_ushort(l1) << 16);
            }
        }
    }
}

// ---------------- fused weight conversion (all 7 transposes, 1 launch) ------
struct WTab {
    const float* W[7];
    __nv_bfloat16* Th[7];
    __nv_bfloat16* Tl[7];
    int K[7];     // GEMM-K (= rows of stored W)
    int N[7];     // cols of stored W
    int off[8];   // tile prefix offsets
};

__global__ void convWT_all(WTab tab)
{
    __shared__ float t[32][33];
    int bid = blockIdx.x;
    int e = 0;
    #pragma unroll
    for (int i = 1; i < 7; i++) if (bid >= tab.off[i]) e = i;
    int local = bid - tab.off[e];
    const float* W = tab.W[e];
    __nv_bfloat16* Th = tab.Th[e];
    __nv_bfloat16* Tl = tab.Tl[e];
    int K = tab.K[e], N = tab.N[e];
    int ntiles = N >> 5;
    int kt = local / ntiles, ct = local - kt*ntiles;
    int by = kt*32, bx = ct*32;
    int lx = threadIdx.x & 31, ly = threadIdx.x >> 5;
    #pragma unroll
    for (int i = 0; i < 32; i += 8)
        t[ly + i][lx] = W[(size_t)(by + ly + i)*N + bx + lx];
    __syncthreads();
    #pragma unroll
    for (int i = 0; i < 32; i += 8){
        int n = bx + ly + i, k = by + lx;
        float x = t[lx][ly + i];
        __nv_bfloat16 h = __float2bfloat16_rn(x);
        Th[(size_t)n*K + k] = h;
        Tl[(size_t)n*K + k] = __float2bfloat16_rn(x - __bfloat162float(h));
    }
}

__global__ void convA(const float* __restrict__ X, __nv_bfloat16* __restrict__ H,
                      __nv_bfloat16* __restrict__ L, int n)
{
    int i = blockIdx.x*256 + threadIdx.x;
    if (i < n){
        float x = X[i];
        __nv_bfloat16 h = __float2bfloat16_rn(x);
        H[i] = h;
        L[i] = __float2bfloat16_rn(x - __bfloat162float(h));
    }
}

// ---------------- LayerNorm -> bf16 hi/lo -----------------------------------
__global__ void ln_bf16(const float* __restrict__ X, const float* __restrict__ g,
                        const float* __restrict__ bt,
                        __nv_bfloat16* __restrict__ Yh, __nv_bfloat16* __restrict__ Yl)
{
    int row = blockIdx.x;
    int tid = threadIdx.x; // 256
    const float* x = X + (size_t)row*EE;
    float a = x[tid], c = x[tid + 256];
    float s  = a + c;
    float s2 = a*a + c*c;
    #pragma unroll
    for (int o = 16; o > 0; o >>= 1){
        s  += __shfl_xor_sync(0xffffffffu, s,  o);
        s2 += __shfl_xor_sync(0xffffffffu, s2, o);
    }
    __shared__ float sa[8], sbm[8];
    if ((tid & 31) == 0){ sa[tid>>5] = s; sbm[tid>>5] = s2; }
    __syncthreads();
    float ts = 0.f, ts2 = 0.f;
    #pragma unroll
    for (int w = 0; w < 8; w++){ ts += sa[w]; ts2 += sbm[w]; }
    float mean = ts * (1.f/512.f);
    float var  = ts2 * (1.f/512.f) - mean*mean;
    float r = rsqrtf(var + 1e-3f);
    float y0 = (a - mean)*r*g[tid]       + bt[tid];
    float y1 = (c - mean)*r*g[tid + 256] + bt[tid + 256];
    __nv_bfloat16 h0 = __float2bfloat16_rn(y0);
    __nv_bfloat16 h1 = __float2bfloat16_rn(y1);
    Yh[(size_t)row*EE + tid]       = h0;
    Yh[(size_t)row*EE + tid + 256] = h1;
    Yl[(size_t)row*EE + tid]       = __float2bfloat16_rn(y0 - __bfloat162float(h0));
    Yl[(size_t)row*EE + tid + 256] = __float2bfloat16_rn(y1 - __bfloat162float(h1));
}

// ---------------- tiny N=8 projection ---------------------------------------
__global__ void proj8(const float* __restrict__ X, const float* __restrict__ Wp,
                      const float* __restrict__ bp, float* __restrict__ Y)
{
    int row = blockIdx.x;
    int tid = threadIdx.x;
    int h = tid & 7, seg = tid >> 3;
    const float* x = X + (size_t)row*EE;
    float s = 0.f;
    #pragma unroll
    for (int k = 0; k < 16; k++){
        int kk = seg*16 + k;
        s += x[kk] * Wp[kk*HH + h];
    }
    __shared__ float sm[256];
    sm[tid] = s;
    __syncthreads();
    if (tid < 8){
        float acc = bp[tid];
        #pragma unroll
        for (int sg = 0; sg < 32; sg++) acc += sm[sg*8 + tid];
        Y[(size_t)row*HH + tid] = acc;
    }
}

// ---------------- P[m,h,r] --------------------------------------------------
__global__ __launch_bounds__(128) void pkernel(
    const float* __restrict__ q, const float* __restrict__ krt,
    const float* __restrict__ t1, float* __restrict__ P)
{
    int h = blockIdx.y;
    int m = blockIdx.x * 128 + threadIdx.x;
    float qr[64];
    const float4* qp = (const float4*)(q + (size_t)m*EE + h*DD);
    #pragma unroll
    for (int t = 0; t < 16; t++){
        float4 v = qp[t];
        qr[t*4+0]=v.x; qr[t*4+1]=v.y; qr[t*4+2]=v.z; qr[t*4+3]=v.w;
    }
    float* Pp = P + ((size_t)m*HH + h)*RUSE;
    const float* kbase = krt + h*DD;
    for (int r = 0; r < RUSE; r++){
        const float4* kp = (const float4*)(kbase + (size_t)r*EE);
        float acc = 0.f;
        #pragma unroll
        for (int t = 0; t < 16; t++){
            float4 k4 = __ldg(&kp[t]);
            acc += qr[t*4+0]*k4.x + qr[t*4+1]*k4.y + qr[t*4+2]*k4.z + qr[t*4+3]*k4.w;
        }
        Pp[r] = acc + t1[r*HH + h];
    }
}

// ---------------- logits ----------------------------------------------------
__global__ __launch_bounds__(256) void logits_kernel(
    const float* __restrict__ q, const float* __restrict__ ke,
    const float* __restrict__ P, const float* __restrict__ b0t,
    float* __restrict__ L)
{
    int jt = blockIdx.x, it = blockIdx.y;
    if (jt > it) return;
    int bh = blockIdx.z; int b = bh >> 3, h = bh & 7;
    __shared__ float Qs[64][68];
    __shared__ float Ks[64][68];
    int tid = threadIdx.x;
    int i0 = it*64, j0 = jt*64;
    #pragma unroll
    for (int l = 0; l < 4; l++){
        int idx = tid + l*256;
        int r = idx >> 4, c4 = (idx & 15) << 2;
        float4 qv = *(const float4*)&q[((size_t)(b*SS + i0 + r))*EE + h*DD + c4];
        Qs[c4+0][r]=qv.x; Qs[c4+1][r]=qv.y; Qs[c4+2][r]=qv.z; Qs[c4+3][r]=qv.w;
        float4 kv4 = *(const float4*)&ke[((size_t)(b*SS + j0 + r))*EE + h*DD + c4];
        Ks[c4+0][r]=kv4.x; Ks[c4+1][r]=kv4.y; Ks[c4+2][r]=kv4.z; Ks[c4+3][r]=kv4.w;
    }
    __syncthreads();
    int tx = tid & 15, ty = tid >> 4;
    float acc[4][4] = {};
    #pragma unroll
    for (int d = 0; d < 64; d++){
        float4 a  = *(const float4*)&Qs[d][ty*4];
        float4 bv = *(const float4*)&Ks[d][tx*4];
        float av[4] = {a.x, a.y, a.z, a.w};
        float bb2[4] = {bv.x, bv.y, bv.z, bv.w};
        #pragma unroll
        for (int i = 0; i < 4; i++)
            #pragma unroll
            for (int j = 0; j < 4; j++)
                acc[i][j] += av[i] * bb2[j];
    }
    #pragma unroll
    for (int i = 0; i < 4; i++){
        int gi = i0 + ty*4 + i;
        const float* Pr = P + ((size_t)(b*SS + gi)*HH + h)*RUSE;
        #pragma unroll
        for (int j = 0; j < 4; j++){
            int gj = j0 + tx*4 + j;
            float val;
            if (gj > gi){
                val = -1e9f;
            } else {
                int off = gj - gi;
                if (off < -100) off = -100;
                off += 100;
                val = acc[i][j]*0.125f + Pr[off] + b0t[(size_t)(b*SS + gj)*HH + h];
            }
            L[((size_t)bh*SS + gi)*SS + gj] = val;
        }
    }
}

// ---------------- softmax ---------------------------------------------------
__global__ void softmax_kernel(float* __restrict__ L)
{
    int i = blockIdx.x;
    float* row = L + ((size_t)blockIdx.y*SS + i)*SS;
    int n = i + 1;
    int tid = threadIdx.x;
    float v[4];
    float mx = -1e30f;
    #pragma unroll
    for (int l = 0; l < 4; l++){
        int j = tid + l*128;
        v[l] = (j < n) ? row[j] : -1e30f;
        mx = fmaxf(mx, v[l]);
    }
    #pragma unroll
    for (int o = 16; o > 0; o >>= 1) mx = fmaxf(mx, __shfl_xor_sync(0xffffffffu, mx, o));
    __shared__ float smx[4], ssum[4];
    if ((tid & 31) == 0) smx[tid>>5] = mx;
    __syncthreads();
    mx = fmaxf(fmaxf(smx[0], smx[1]), fmaxf(smx[2], smx[3]));
    float s = 0.f;
    #pragma unroll
    for (int l = 0; l < 4; l++){
        int j = tid + l*128;
        if (j < n){ v[l] = __expf(v[l] - mx); s += v[l]; } else v[l] = 0.f;
    }
    #pragma unroll
    for (int o = 16; o > 0; o >>= 1) s += __shfl_xor_sync(0xffffffffu, s, o);
    if ((tid & 31) == 0) ssum[tid>>5] = s;
    __syncthreads();
    s = ssum[0] + ssum[1] + ssum[2] + ssum[3];
    float inv = 1.f / s;
    #pragma unroll
    for (int l = 0; l < 4; l++){
        int j = tid + l*128;
        if (j < n) row[j] = v[l] * inv;
    }
}

// ---------------- att -------------------------------------------------------
__global__ __launch_bounds__(256) void att_kernel(
    const float* __restrict__ Sc, const float* __restrict__ kv,
    const float* __restrict__ vals, float* __restrict__ V)
{
    int it = blockIdx.x;
    int bh = blockIdx.y; int b = bh >> 3, h = bh & 7;
    int i0 = it*64;
    __shared__ float Ssm[64][68];
    __shared__ float Vsm[64][68];
    int tid = threadIdx.x, tx = tid & 15, ty = tid >> 4;
    float acc[4][4] = {};
    for (int jt = 0; jt <= it; jt++){
        int j0 = jt*64;
        __syncthreads();
        #pragma unroll
        for (int l = 0; l < 4; l++){
            int idx = tid + l*256;
            int r = idx >> 4, c4 = (idx & 15) << 2;
            int gi = i0 + r;
            float4 sv = *(const float4*)&Sc[((size_t)bh*SS + gi)*SS + j0 + c4];
            int gj = j0 + c4;
            if (gj + 0 > gi) sv.x = 0.f;
            if (gj + 1 > gi) sv.y = 0.f;
            if (gj + 2 > gi) sv.z = 0.f;
            if (gj + 3 > gi) sv.w = 0.f;
            Ssm[c4+0][r]=sv.x; Ssm[c4+1][r]=sv.y; Ssm[c4+2][r]=sv.z; Ssm[c4+3][r]=sv.w;
            float4 vv = *(const float4*)&kv[((size_t)(b*SS + j0 + r))*EE + h*DD + c4];
            *(float4*)&Vsm[r][c4] = vv;
        }
        __syncthreads();
        #pragma unroll
        for (int jj = 0; jj < 64; jj++){
            float4 a  = *(const float4*)&Ssm[jj][ty*4];
            float4 bv = *(const float4*)&Vsm[jj][tx*4];
            float av[4] = {a.x, a.y, a.z, a.w};
            float bb2[4] = {bv.x, bv.y, bv.z, bv.w};
            #pragma unroll
            for (int i = 0; i < 4; i++)
                #pragma unroll
                for (int j = 0; j < 4; j++)
                    acc[i][j] += av[i] * bb2[j];
        }
    }
    #pragma unroll
    for (int i = 0; i < 4; i++){
        int gi = i0 + ty*4 + i;
        size_t o = ((size_t)(b*SS + gi))*EE + h*DD + tx*4;
        float4 rv = *(const float4*)&vals[o];
        float4 ov = make_float4(acc[i][0]+rv.x, acc[i][1]+rv.y, acc[i][2]+rv.z, acc[i][3]+rv.w);
        *(float4*)&V[o] = ov;
    }
}

// ---------------- launch ----------------------------------------------------
extern "C" void kernel_launch(void* const* d_in, const int* in_sizes, int n_in,
                              void* d_out, int out_size)
{
    const float* values  = (const float*)d_in[0];
    const float* rel_enc = (const float*)d_in[2];
    const float* ln0_g   = (const float*)d_in[3];
    const float* ln0_b   = (const float*)d_in[4];
    const float* w_b0    = (const float*)d_in[5];
    const float* b_b0    = (const float*)d_in[6];
    const float* wq      = (const float*)d_in[7];
    const float* bq      = (const float*)d_in[8];
    const float* wke     = (const float*)d_in[9];
    const float* bke     = (const float*)d_in[10];
    const float* wkv     = (const float*)d_in[11];
    const float* bkv     = (const float*)d_in[12];
    const float* wkr     = (const float*)d_in[13];
    const float* bkr     = (const float*)d_in[14];
    const float* wab0    = (const float*)d_in[15];
    const float* bab0    = (const float*)d_in[16];
    const float* wab1    = (const float*)d_in[17];
    const float* bab1    = (const float*)d_in[18];
    const float* ln1_g   = (const float*)d_in[19];
    const float* ln1_b   = (const float*)d_in[20];
    const float* w11     = (const float*)d_in[21];
    const float* b11     = (const float*)d_in[22];
    const float* w12     = (const float*)d_in[23];
    const float* b12     = (const float*)d_in[24];
    float* out = (float*)d_out;

    float *p_q,*p_ke,*p_kv,*p_krt,*p_t1,*p_b0t,*p_P,*p_L,*p_v;
    cudaGetSymbolAddress((void**)&p_q,   g_q);
    cudaGetSymbolAddress((void**)&p_ke,  g_ke);
    cudaGetSymbolAddress((void**)&p_kv,  g_kv);
    cudaGetSymbolAddress((void**)&p_krt, g_krt);
    cudaGetSymbolAddress((void**)&p_t1,  g_t1);
    cudaGetSymbolAddress((void**)&p_b0t, g_b0t);
    cudaGetSymbolAddress((void**)&p_P,   g_P);
    cudaGetSymbolAddress((void**)&p_L,   g_L);
    cudaGetSymbolAddress((void**)&p_v,   g_v);

    __nv_bfloat16 *xnh,*xnl,*xh,*xl,*vnh,*vnl,*h1h,*h1l,*reh,*rel;
    __nv_bfloat16 *wb0h,*wb0l,*wqh,*wql,*wkeh,*wkel,*wkvh,*wkvl,*wkrh,*wkrl,*w11h,*w11l,*w12h,*w12l;
    cudaGetSymbolAddress((void**)&xnh, g_xnh); cudaGetSymbolAddress((void**)&xnl, g_xnl);
    cudaGetSymbolAddress((void**)&xh,  g_xh);  cudaGetSymbolAddress((void**)&xl,  g_xl);
    cudaGetSymbolAddress((void**)&vnh, g_vnh); cudaGetSymbolAddress((void**)&vnl, g_vnl);
    cudaGetSymbolAddress((void**)&h1h, g_h1h); cudaGetSymbolAddress((void**)&h1l, g_h1l);
    cudaGetSymbolAddress((void**)&reh, g_reh); cudaGetSymbolAddress((void**)&rel, g_rel_);
    cudaGetSymbolAddress((void**)&wb0h, g_wb0h); cudaGetSymbolAddress((void**)&wb0l, g_wb0l);
    cudaGetSymbolAddress((void**)&wqh,  g_wqh);  cudaGetSymbolAddress((void**)&wql,  g_wql);
    cudaGetSymbolAddress((void**)&wkeh, g_wkeh); cudaGetSymbolAddress((void**)&wkel, g_wkel);
    cudaGetSymbolAddress((void**)&wkvh, g_wkvh); cudaGetSymbolAddress((void**)&wkvl, g_wkvl);
    cudaGetSymbolAddress((void**)&wkrh, g_wkrh); cudaGetSymbolAddress((void**)&wkrl, g_wkrl);
    cudaGetSymbolAddress((void**)&w11h, g_w11h); cudaGetSymbolAddress((void**)&w11l, g_w11l);
    cudaGetSymbolAddress((void**)&w12h, g_w12h); cudaGetSymbolAddress((void**)&w12l, g_w12l);

    cudaFuncSetAttribute(gemm_tc<0>,  cudaFuncAttributeMaxDynamicSharedMemorySize, GSMEM_BYTES);
    cudaFuncSetAttribute(gemm_tc<2>,  cudaFuncAttributeMaxDynamicSharedMemorySize, GSMEM_BYTES);
    cudaFuncSetAttribute(gemm_qkv_tc, cudaFuncAttributeMaxDynamicSharedMemorySize, GSMEM_BYTES);
    cudaFuncSetAttribute(gemm_big_relu, cudaFuncAttributeMaxDynamicSharedMemorySize, GSMEM2_BYTES);

    // ---- fused weight conversion (1 launch for all 7 transposes) ----
    WTab tab;
    tab.W[0]=w_b0; tab.Th[0]=wb0h; tab.Tl[0]=wb0l; tab.K[0]=EE;   tab.N[0]=HIDD;
    tab.W[1]=wq;   tab.Th[1]=wqh;  tab.Tl[1]=wql;  tab.K[1]=HIDD; tab.N[1]=EE;
    tab.W[2]=wke;  tab.Th[2]=wkeh; tab.Tl[2]=wkel; tab.K[2]=HIDD; tab.N[2]=EE;
    tab.W[3]=wkv;  tab.Th[3]=wkvh; tab.Tl[3]=wkvl; tab.K[3]=HIDD; tab.N[3]=EE;
    tab.W[4]=wkr;  tab.Th[4]=wkrh; tab.Tl[4]=wkrl; tab.K[4]=EE;   tab.N[4]=EE;
    tab.W[5]=w11;  tab.Th[5]=w11h; tab.Tl[5]=w11l; tab.K[5]=EE;   tab.N[5]=HIDD;
    tab.W[6]=w12;  tab.Th[6]=w12h; tab.Tl[6]=w12l; tab.K[6]=HIDD; tab.N[6]=EE;
    int total = 0;
    for (int i = 0; i < 7; i++){
        tab.off[i] = total;
        total += (tab.K[i]/32) * (tab.N[i]/32);
    }
    tab.off[7] = total;
    convWT_all<<<total, 256>>>(tab);
    convA<<<(RFULL*EE + 255)/256, 256>>>(rel_enc, reh, rel, RFULL*EE);

    // 1) LN0 -> bf16 hi/lo
    ln_bf16<<<MR, 256>>>(values, ln0_g, ln0_b, xnh, xnl);
    // 2) x = relu(xn @ w_b0 + b_b0) -> bf16 hi/lo  [128x256 tiles, 1 wave]
    gemm_big_relu<<<dim3(HIDD/256, MR/128), 256, GSMEM2_BYTES>>>(
        xnh, xnl, wb0h, wb0l, b_b0, xh, xl, MR, HIDD, EE);
    // 3) q / ke / kv (fp32 out)
    gemm_qkv_tc<<<dim3(EE/128, MR/128, 3), 256, GSMEM_BYTES>>>(
        xh, xl, wqh, wql, wkeh, wkel, wkvh, wkvl, bq, bke, bkv,
        p_q, p_ke, p_kv, MR, EE, HIDD);
    // 4) kr_table = rel_enc @ wkr + bkr  (M=201)
    gemm_tc<0><<<dim3(EE/128, 2), 256, GSMEM_BYTES>>>(
        reh, rel, wkrh, wkrl, bkr, nullptr, p_krt, nullptr, nullptr, RFULL, EE, EE);
    // 5) t1 / bias0
    proj8<<<RFULL, 256>>>(p_krt, wab1, bab1, p_t1);
    proj8<<<MR, 256>>>(p_ke, wab0, bab0, p_b0t);
    // 7) P
    pkernel<<<dim3(MR/128, HH), 128>>>(p_q, p_krt, p_t1, p_P);
    // 8) logits
    logits_kernel<<<dim3(8, 8, BB*HH), 256>>>(p_q, p_ke, p_P, p_b0t, p_L);
    // 9) softmax
    softmax_kernel<<<dim3(SS, BB*HH), 128>>>(p_L);
    // 10) att + residual
    att_kernel<<<dim3(8, BB*HH), 256>>>(p_L, p_kv, values, p_v);
    // 11) LN1 -> bf16
    ln_bf16<<<MR, 256>>>(p_v, ln1_g, ln1_b, vnh, vnl);
    // 12) h1 = relu(vn @ w11 + b11) -> bf16  [128x256 tiles, 1 wave]
    gemm_big_relu<<<dim3(HIDD/256, MR/128), 256, GSMEM2_BYTES>>>(
        vnh, vnl, w11h, w11l, b11, h1h, h1l, MR, HIDD, EE);
    // 13) out = v + h1 @ w12 + b12
    gemm_tc<2><<<dim3(EE/128, MR/128), 256, GSMEM_BYTES>>>(
        h1h, h1l, w12h, w12l, b12, p_v, out, nullptr, nullptr, MR, EE, HIDD);
}

// round 6
// speedup vs baseline: 1.9926x; 1.0448x over previous
#include <cuda_runtime.h>
#include <cuda_bf16.h>
#include <cstdint>
#include <cstddef>

#define BB 4
#define SS 512
#define EE 512
#define HIDD 2048
#define HH 8
#define DD 64
#define RFULL 201
#define RUSE 101
#define MR (BB*SS)   // 2048

// ---------------- fp32 scratch ----------------------------------------------
__device__ __align__(128) float g_q [MR*EE];
__device__ __align__(128) float g_ke[MR*EE];
__device__ __align__(128) float g_kv[MR*EE];
__device__ __align__(128) float g_krt[RFULL*EE];
__device__ __align__(128) float g_t1[RFULL*HH];
__device__ __align__(128) float g_b0t[MR*HH];
__device__ __align__(128) float g_P[(size_t)MR*HH*RUSE];
__device__ __align__(128) float g_L[(size_t)BB*HH*SS*SS];
__device__ __align__(128) float g_v [MR*EE];

// ---------------- bf16 split scratch ----------------------------------------
__device__ __align__(128) __nv_bfloat16 g_xnh[MR*EE],   g_xnl[MR*EE];
__device__ __align__(128) __nv_bfloat16 g_xh [MR*HIDD], g_xl [MR*HIDD];
__device__ __align__(128) __nv_bfloat16 g_vnh[MR*EE],   g_vnl[MR*EE];
__device__ __align__(128) __nv_bfloat16 g_h1h[MR*HIDD], g_h1l[MR*HIDD];
__device__ __align__(128) __nv_bfloat16 g_reh[RFULL*EE + 64], g_rel_[RFULL*EE + 64];
__device__ __align__(128) __nv_bfloat16 g_qh [MR*EE], g_ql [MR*EE];
__device__ __align__(128) __nv_bfloat16 g_keh[MR*EE], g_kel[MR*EE];
__device__ __align__(128) __nv_bfloat16 g_kvh[MR*EE], g_kvl[MR*EE];
__device__ __align__(128) __nv_bfloat16 g_Ph[(size_t)BB*HH*SS*SS];
__device__ __align__(128) __nv_bfloat16 g_Pl[(size_t)BB*HH*SS*SS];
// weights, transposed to [N][K] and split
__device__ __align__(128) __nv_bfloat16 g_wb0h[HIDD*EE], g_wb0l[HIDD*EE];
__device__ __align__(128) __nv_bfloat16 g_wqh [EE*HIDD], g_wql [EE*HIDD];
__device__ __align__(128) __nv_bfloat16 g_wkeh[EE*HIDD], g_wkel[EE*HIDD];
__device__ __align__(128) __nv_bfloat16 g_wkvh[EE*HIDD], g_wkvl[EE*HIDD];
__device__ __align__(128) __nv_bfloat16 g_wkrh[EE*EE],   g_wkrl[EE*EE];
__device__ __align__(128) __nv_bfloat16 g_w11h[HIDD*EE], g_w11l[HIDD*EE];
__device__ __align__(128) __nv_bfloat16 g_w12h[EE*HIDD], g_w12l[EE*HIDD];

// ---------------- PTX helpers (portable sm_80-class PTX only) ---------------
__device__ __forceinline__ uint32_t s2u(const void* p){
    uint32_t a;
    asm("{ .reg .u64 t; cvta.to.shared.u64 t, %1; cvt.u32.u64 %0, t; }" : "=r"(a) : "l"(p));
    return a;
}
__device__ __forceinline__ void cpa16(uint32_t dst, const void* src, uint32_t sz){
    asm volatile("cp.async.cg.shared.global [%0], [%1], 16, %2;" :: "r"(dst), "l"(src), "r"(sz));
}
__device__ __forceinline__ void cpcommit(){ asm volatile("cp.async.commit_group;" ::: "memory"); }
__device__ __forceinline__ void cpwait0(){ asm volatile("cp.async.wait_group 0;" ::: "memory"); }
__device__ __forceinline__ void cpwait1(){ asm volatile("cp.async.wait_group 1;" ::: "memory"); }
__device__ __forceinline__ void cpwait2(){ asm volatile("cp.async.wait_group 2;" ::: "memory"); }

__device__ __forceinline__ void ldsm4(uint32_t* r, uint32_t addr){
    asm volatile("ldmatrix.sync.aligned.m8n8.x4.shared.b16 {%0,%1,%2,%3}, [%4];"
        : "=r"(r[0]), "=r"(r[1]), "=r"(r[2]), "=r"(r[3]) : "r"(addr));
}
__device__ __forceinline__ void ldsm4t(uint32_t* r, uint32_t addr){
    asm volatile("ldmatrix.sync.aligned.m8n8.x4.trans.shared.b16 {%0,%1,%2,%3}, [%4];"
        : "=r"(r[0]), "=r"(r[1]), "=r"(r[2]), "=r"(r[3]) : "r"(addr));
}
__device__ __forceinline__ void mma16816(float* d, const uint32_t* a, const uint32_t* b){
    asm volatile("mma.sync.aligned.m16n8k16.row.col.f32.bf16.bf16.f32 "
        "{%0,%1,%2,%3}, {%4,%5,%6,%7}, {%8,%9}, {%0,%1,%2,%3};"
        : "+f"(d[0]), "+f"(d[1]), "+f"(d[2]), "+f"(d[3])
        : "r"(a[0]), "r"(a[1]), "r"(a[2]), "r"(a[3]), "r"(b[0]), "r"(b[1]));
}

__device__ __forceinline__ void split_bf16(float v, uint32_t lane_even, __nv_bfloat16& h, __nv_bfloat16& l){
    h = __float2bfloat16_rn(v);
    l = __float2bfloat16_rn(v - __bfloat162float(h));
}

// shared geometry: k-chunk 32, rows padded to 40 bf16 (80 B)
#define KC 32
#define LDSM_STRIDE 40
#define TILE_B (128*LDSM_STRIDE*2)       // 10240 (128-row tile)
#define STAGE_B (4*TILE_B)               // 40960
#define GSMEM_BYTES (3*STAGE_B)          // 122880 (128x128, 3-stage)

#define TILE_A2 (128*LDSM_STRIDE*2)      // 10240
#define TILE_B2 (256*LDSM_STRIDE*2)      // 20480
#define STAGE_B2 (2*TILE_A2 + 2*TILE_B2) // 61440
#define GSMEM2_BYTES (3*STAGE_B2)        // 184320 (128x256, 3-stage)

// attention tile geometry: 64 rows x 64 cols bf16, padded to 72 elems (144 B)
#define ASTRIDE 72
#define ATILE_B (64*ASTRIDE*2)           // 9216
#define ASTAGE_B (4*ATILE_B)             // 36864
#define ATT_SMEM (2*ASTAGE_B)            // 73728

// ---------------- chunk loader (128x128) ------------------------------------
__device__ __forceinline__ void load_chunk(uint32_t stage, int tid,
    const __nv_bfloat16* __restrict__ Ah, const __nv_bfloat16* __restrict__ Al,
    const __nv_bfloat16* __restrict__ Bh, const __nv_bfloat16* __restrict__ Bl,
    int m0, int n0, int k0, int M, int K)
{
    #pragma unroll
    for (int t = 0; t < 4; t++){
        const __nv_bfloat16* g = (t==0)?Ah:(t==1)?Al:(t==2)?Bh:Bl;
        int row0 = (t < 2) ? m0 : n0;
        uint32_t tb = stage + t*TILE_B;
        #pragma unroll
        for (int i = 0; i < 2; i++){
            int s = i*256 + tid;
            int r = s >> 2, seg = s & 3;
            uint32_t dst = tb + (uint32_t)(r*80 + seg*16);
            int gr = row0 + r;
            uint32_t sz = 16u;
            if (t < 2 && gr >= M){ sz = 0u; gr = M - 1; }
            cpa16(dst, (const char*)(g + (size_t)gr*K + k0) + seg*16, sz);
        }
    }
    cpcommit();
}

// ---------------- chunk loader (128x256) ------------------------------------
__device__ __forceinline__ void load_chunk_big(uint32_t stage, int tid,
    const __nv_bfloat16* __restrict__ Ah, const __nv_bfloat16* __restrict__ Al,
    const __nv_bfloat16* __restrict__ Bh, const __nv_bfloat16* __restrict__ Bl,
    int m0, int n0, int k0, int M, int K)
{
    #pragma unroll
    for (int t = 0; t < 2; t++){
        const __nv_bfloat16* g = t ? Al : Ah;
        uint32_t tb = stage + t*TILE_A2;
        #pragma unroll
        for (int i = 0; i < 2; i++){
            int s = i*256 + tid;
            int r = s >> 2, seg = s & 3;
            int gr = m0 + r;
            uint32_t sz = 16u;
            if (gr >= M){ sz = 0u; gr = M - 1; }
            cpa16(tb + (uint32_t)(r*80 + seg*16),
                  (const char*)(g + (size_t)gr*K + k0) + seg*16, sz);
        }
    }
    #pragma unroll
    for (int t = 0; t < 2; t++){
        const __nv_bfloat16* g = t ? Bl : Bh;
        uint32_t tb = stage + 2*TILE_A2 + t*TILE_B2;
        #pragma unroll
        for (int i = 0; i < 4; i++){
            int s = i*256 + tid;
            int r = s >> 2, seg = s & 3;
            cpa16(tb + (uint32_t)(r*80 + seg*16),
                  (const char*)(g + (size_t)(n0 + r)*K + k0) + seg*16, 16u);
        }
    }
    cpcommit();
}

// ---------------- 128x128 split-bf16 GEMM -----------------------------------
// EPI: 0 fp32+bias, 2 fp32+bias+res, 3 fp32 + bf16 hi/lo
template<int EPI>
__device__ void gemm_body(
    const __nv_bfloat16* __restrict__ Ah, const __nv_bfloat16* __restrict__ Al,
    const __nv_bfloat16* __restrict__ Bh, const __nv_bfloat16* __restrict__ Bl,
    const float* __restrict__ bias, const float* __restrict__ res,
    float* __restrict__ Cf, __nv_bfloat16* __restrict__ Ch, __nv_bfloat16* __restrict__ Cl,
    int M, int N, int K)
{
    extern __shared__ char smem[];
    uint32_t sb = s2u(smem);
    int tid = threadIdx.x;
    int lane = tid & 31, warp = tid >> 5;
    int wm = warp >> 2, wn = warp & 3;
    int m0 = blockIdx.y*128, n0 = blockIdx.x*128;

    int a_row  = wm*64 + (lane & 15);
    int a_col8 = (lane >> 4) * 8;
    int b_row  = wn*32 + (lane & 7) + ((lane & 16) ? 8 : 0);
    int b_col8 = ((lane & 8) ? 8 : 0);

    float acc[4][4][4];
    #pragma unroll
    for (int a = 0; a < 4; a++)
        #pragma unroll
        for (int b = 0; b < 4; b++)
            #pragma unroll
            for (int c = 0; c < 4; c++) acc[a][b][c] = 0.f;

    const int NC = K >> 5;
    uint32_t stg0 = sb, stg1 = sb + STAGE_B, stg2 = sb + 2*STAGE_B;

    load_chunk(stg0, tid, Ah, Al, Bh, Bl, m0, n0, 0, M, K);
    if (NC > 1) load_chunk(stg1, tid, Ah, Al, Bh, Bl, m0, n0, KC, M, K);

    for (int c = 0; c < NC; c++){
        if (c + 2 < NC){
            int s = (c + 2) % 3;
            load_chunk(s == 0 ? stg0 : (s == 1 ? stg1 : stg2),
                       tid, Ah, Al, Bh, Bl, m0, n0, (c+2)*KC, M, K);
        }
        if (c + 2 < NC) cpwait2(); else if (c + 1 < NC) cpwait1(); else cpwait0();
        __syncthreads();
        int cm = c % 3;
        uint32_t cur = cm == 0 ? stg0 : (cm == 1 ? stg1 : stg2);

        uint32_t cAh = cur, cAl = cur + TILE_B, cBh = cur + 2*TILE_B, cBl = cur + 3*TILE_B;
        #pragma unroll
        for (int ks = 0; ks < 2; ks++){
            int k0 = ks*16;
            uint32_t ah[4][4], al[4][4], bh[2][4], bl[2][4];
            #pragma unroll
            for (int mt = 0; mt < 4; mt++){
                uint32_t off = (uint32_t)(((a_row + mt*16)*LDSM_STRIDE) + k0 + a_col8) * 2u;
                ldsm4(ah[mt], cAh + off);
                ldsm4(al[mt], cAl + off);
            }
            #pragma unroll
            for (int p = 0; p < 2; p++){
                uint32_t off = (uint32_t)(((b_row + p*16)*LDSM_STRIDE) + k0 + b_col8) * 2u;
                ldsm4(bh[p], cBh + off);
                ldsm4(bl[p], cBl + off);
            }
            #pragma unroll
            for (int mt = 0; mt < 4; mt++)
                #pragma unroll
                for (int nt = 0; nt < 4; nt++){
                    const uint32_t* bhp = &bh[nt >> 1][(nt & 1)*2];
                    const uint32_t* blp = &bl[nt >> 1][(nt & 1)*2];
                    mma16816(acc[mt][nt], ah[mt], bhp);
                    mma16816(acc[mt][nt], ah[mt], blp);
                    mma16816(acc[mt][nt], al[mt], bhp);
                }
        }
        __syncthreads();
    }

    int g = lane >> 2, tig = lane & 3;
    #pragma unroll
    for (int mt = 0; mt < 4; mt++){
        #pragma unroll
        for (int half = 0; half < 2; half++){
            int row = m0 + wm*64 + mt*16 + g + half*8;
            if (row >= M) continue;
            #pragma unroll
            for (int nt = 0; nt < 4; nt++){
                int col = n0 + wn*32 + nt*8 + tig*2;
                float v0 = acc[mt][nt][half*2 + 0] + bias[col];
                float v1 = acc[mt][nt][half*2 + 1] + bias[col + 1];
                size_t o = (size_t)row*N + col;
                if (EPI == 2){
                    float2 rv = *(const float2*)&res[o];
                    v0 += rv.x; v1 += rv.y;
                }
                *(float2*)&Cf[o] = make_float2(v0, v1);
                if (EPI == 3){
                    __nv_bfloat16 h0 = __float2bfloat16_rn(v0);
                    __nv_bfloat16 h1 = __float2bfloat16_rn(v1);
                    __nv_bfloat16 l0 = __float2bfloat16_rn(v0 - __bfloat162float(h0));
                    __nv_bfloat16 l1 = __float2bfloat16_rn(v1 - __bfloat162float(h1));
                    *(uint32_t*)((char*)Ch + o*2) =
                        (uint32_t)__bfloat16_as_ushort(h0) | ((uint32_t)__bfloat16_as_ushort(h1) << 16);
                    *(uint32_t*)((char*)Cl + o*2) =
                        (uint32_t)__bfloat16_as_ushort(l0) | ((uint32_t)__bfloat16_as_ushort(l1) << 16);
                }
            }
        }
    }
}

template<int EPI>
__global__ __launch_bounds__(256, 1)
void gemm_tc(const __nv_bfloat16* Ah, const __nv_bfloat16* Al,
             const __nv_bfloat16* Bh, const __nv_bfloat16* Bl,
             const float* bias, const float* res,
             float* Cf, __nv_bfloat16* Ch, __nv_bfloat16* Cl, int M, int N, int K)
{
    gemm_body<EPI>(Ah, Al, Bh, Bl, bias, res, Cf, Ch, Cl, M, N, K);
}

__global__ __launch_bounds__(256, 1)
void gemm_qkv_tc(const __nv_bfloat16* Ah, const __nv_bfloat16* Al,
                 const __nv_bfloat16* B0h, const __nv_bfloat16* B0l,
                 const __nv_bfloat16* B1h, const __nv_bfloat16* B1l,
                 const __nv_bfloat16* B2h, const __nv_bfloat16* B2l,
                 const float* b0, const float* b1, const float* b2,
                 float* C0, float* C1, float* C2,
                 __nv_bfloat16* C0h, __nv_bfloat16* C0l,
                 __nv_bfloat16* C1h, __nv_bfloat16* C1l,
                 __nv_bfloat16* C2h, __nv_bfloat16* C2l,
                 int M, int N, int K)
{
    int z = blockIdx.z;
    const __nv_bfloat16* Bh = (z==0)?B0h:(z==1)?B1h:B2h;
    const __nv_bfloat16* Bl = (z==0)?B0l:(z==1)?B1l:B2l;
    const float* bias = (z==0)?b0:(z==1)?b1:b2;
    float* C = (z==0)?C0:(z==1)?C1:C2;
    __nv_bfloat16* Ch = (z==0)?C0h:(z==1)?C1h:C2h;
    __nv_bfloat16* Cl = (z==0)?C0l:(z==1)?C1l:C2l;
    gemm_body<3>(Ah, Al, Bh, Bl, bias, nullptr, C, Ch, Cl, M, N, K);
}

// ---------------- 128x256 split-bf16 GEMM, relu -> bf16 hi/lo ---------------
__global__ __launch_bounds__(256, 1)
void gemm_big_relu(const __nv_bfloat16* __restrict__ Ah, const __nv_bfloat16* __restrict__ Al,
                   const __nv_bfloat16* __restrict__ Bh, const __nv_bfloat16* __restrict__ Bl,
                   const float* __restrict__ bias,
                   __nv_bfloat16* __restrict__ Ch, __nv_bfloat16* __restrict__ Cl,
                   int M, int N, int K)
{
    extern __shared__ char smem[];
    uint32_t sb = s2u(smem);
    int tid = threadIdx.x;
    int lane = tid & 31, warp = tid >> 5;
    int wm = warp >> 2;
    int wn = warp & 3;
    int m0 = blockIdx.y*128, n0 = blockIdx.x*256;

    int a_row  = wm*64 + (lane & 15);
    int a_col8 = (lane >> 4) * 8;
    int b_rowb = wn*64 + (lane & 7) + ((lane & 16) ? 8 : 0);
    int b_col8 = ((lane & 8) ? 8 : 0);

    float acc[4][8][4];
    #pragma unroll
    for (int a = 0; a < 4; a++)
        #pragma unroll
        for (int b = 0; b < 8; b++)
            #pragma unroll
            for (int c = 0; c < 4; c++) acc[a][b][c] = 0.f;

    const int NC = K >> 5;
    uint32_t stg0 = sb, stg1 = sb + STAGE_B2, stg2 = sb + 2*STAGE_B2;

    load_chunk_big(stg0, tid, Ah, Al, Bh, Bl, m0, n0, 0, M, K);
    if (NC > 1) load_chunk_big(stg1, tid, Ah, Al, Bh, Bl, m0, n0, KC, M, K);

    for (int c = 0; c < NC; c++){
        if (c + 2 < NC){
            int s = (c + 2) % 3;
            load_chunk_big(s == 0 ? stg0 : (s == 1 ? stg1 : stg2),
                           tid, Ah, Al, Bh, Bl, m0, n0, (c+2)*KC, M, K);
        }
        if (c + 2 < NC) cpwait2(); else if (c + 1 < NC) cpwait1(); else cpwait0();
        __syncthreads();
        int cm = c % 3;
        uint32_t cur = cm == 0 ? stg0 : (cm == 1 ? stg1 : stg2);

        uint32_t cAh = cur, cAl = cur + TILE_A2;
        uint32_t cBh = cur + 2*TILE_A2, cBl = cur + 2*TILE_A2 + TILE_B2;
        #pragma unroll
        for (int ks = 0; ks < 2; ks++){
            int k0 = ks*16;
            uint32_t ah[4][4], al[4][4];
            #pragma unroll
            for (int mt = 0; mt < 4; mt++){
                uint32_t off = (uint32_t)(((a_row + mt*16)*LDSM_STRIDE) + k0 + a_col8) * 2u;
                ldsm4(ah[mt], cAh + off);
                ldsm4(al[mt], cAl + off);
            }
            #pragma unroll
            for (int h2 = 0; h2 < 2; h2++){
                uint32_t bh[2][4], bl[2][4];
                #pragma unroll
                for (int p = 0; p < 2; p++){
                    uint32_t off = (uint32_t)(((b_rowb + (h2*2 + p)*16)*LDSM_STRIDE) + k0 + b_col8) * 2u;
                    ldsm4(bh[p], cBh + off);
                    ldsm4(bl[p], cBl + off);
                }
                #pragma unroll
                for (int mt = 0; mt < 4; mt++)
                    #pragma unroll
                    for (int j = 0; j < 4; j++){
                        const uint32_t* bhp = &bh[j >> 1][(j & 1)*2];
                        const uint32_t* blp = &bl[j >> 1][(j & 1)*2];
                        float* a4 = acc[mt][h2*4 + j];
                        mma16816(a4, ah[mt], bhp);
                        mma16816(a4, ah[mt], blp);
                        mma16816(a4, al[mt], bhp);
                    }
            }
        }
        __syncthreads();
    }

    int g = lane >> 2, tig = lane & 3;
    #pragma unroll
    for (int mt = 0; mt < 4; mt++){
        #pragma unroll
        for (int half = 0; half < 2; half++){
            int row = m0 + wm*64 + mt*16 + g + half*8;
            if (row >= M) continue;
            #pragma unroll
            for (int nt8 = 0; nt8 < 8; nt8++){
                int col = n0 + wn*64 + nt8*8 + tig*2;
                float v0 = fmaxf(acc[mt][nt8][half*2 + 0] + bias[col],     0.f);
                float v1 = fmaxf(acc[mt][nt8][half*2 + 1] + bias[col + 1], 0.f);
                size_t o = (size_t)row*N + col;
                __nv_bfloat16 h0 = __float2bfloat16_rn(v0);
                __nv_bfloat16 h1 = __float2bfloat16_rn(v1);
                __nv_bfloat16 l0 = __float2bfloat16_rn(v0 - __bfloat162float(h0));
                __nv_bfloat16 l1 = __float2bfloat16_rn(v1 - __bfloat162float(h1));
                *(uint32_t*)((char*)Ch + o*2) =
                    (uint32_t)__bfloat16_as_ushort(h0) | ((uint32_t)__bfloat16_as_ushort(h1) << 16);
                *(uint32_t*)((char*)Cl + o*2) =
                    (uint32_t)__bfloat16_as_ushort(l0) | ((uint32_t)__bfloat16_as_ushort(l1) << 16);
            }
        }
    }
}

// ---------------- logits via mma: causal 64x64 tiles ------------------------
__global__ __launch_bounds__(128) void logits_mma(
    const __nv_bfloat16* __restrict__ qh, const __nv_bfloat16* __restrict__ ql,
    const __nv_bfloat16* __restrict__ keh, const __nv_bfloat16* __restrict__ kel,
    const float* __restrict__ P, const float* __restrict__ b0t,
    float* __restrict__ L)
{
    __shared__ char lsm[ASTAGE_B];
    uint32_t sb = s2u(lsm);
    int tid = threadIdx.x;
    int lane = tid & 31, warp = tid >> 5;
    int tri = blockIdx.x;
    int it = 0;
    while ((it + 1)*(it + 2)/2 <= tri) it++;
    int jt = tri - it*(it + 1)/2;
    int bh = blockIdx.y, b = bh >> 3, h = bh & 7;
    int i0 = it*64, j0 = jt*64;

    // load 4 tiles: qh/ql rows i0.., keh/kel rows j0.. ; 64 rows x 64 bf16
    #pragma unroll
    for (int t = 0; t < 4; t++){
        const __nv_bfloat16* g = (t==0)?qh:(t==1)?ql:(t==2)?keh:kel;
        int row0 = (t < 2) ? i0 : j0;
        uint32_t tb = sb + t*ATILE_B;
        #pragma unroll
        for (int i = 0; i < 4; i++){
            int s = i*128 + tid;
            int r = s >> 3, seg = s & 7;
            cpa16(tb + (uint32_t)(r*144 + seg*16),
                  g + ((size_t)(b*SS + row0 + r))*EE + h*DD + seg*8, 16u);
        }
    }
    cpcommit(); cpwait0();
    __syncthreads();

    int wm = warp >> 1, wn = warp & 1;
    int a_row  = wm*32 + (lane & 15);
    int a_col8 = (lane >> 4)*8;
    int b_row  = wn*32 + (lane & 7) + ((lane & 16) ? 8 : 0);
    int b_col8 = ((lane & 8) ? 8 : 0);

    uint32_t cAh = sb, cAl = sb + ATILE_B, cBh = sb + 2*ATILE_B, cBl = sb + 3*ATILE_B;
    float acc[2][4][4];
    #pragma unroll
    for (int a = 0; a < 2; a++)
        #pragma unroll
        for (int bb2 = 0; bb2 < 4; bb2++)
            #pragma unroll
            for (int c = 0; c < 4; c++) acc[a][bb2][c] = 0.f;

    #pragma unroll
    for (int ks = 0; ks < 4; ks++){
        int k0 = ks*16;
        uint32_t ah[2][4], al[2][4], bhf[2][4], blf[2][4];
        #pragma unroll
        for (int mt = 0; mt < 2; mt++){
            uint32_t off = (uint32_t)(((a_row + mt*16)*ASTRIDE) + k0 + a_col8)*2u;
            ldsm4(ah[mt], cAh + off);
            ldsm4(al[mt], cAl + off);
        }
        #pragma unroll
        for (int p = 0; p < 2; p++){
            uint32_t off = (uint32_t)(((b_row + p*16)*ASTRIDE) + k0 + b_col8)*2u;
            ldsm4(bhf[p], cBh + off);
            ldsm4(blf[p], cBl + off);
        }
        #pragma unroll
        for (int mt = 0; mt < 2; mt++)
            #pragma unroll
            for (int nt = 0; nt < 4; nt++){
                const uint32_t* bhp = &bhf[nt >> 1][(nt & 1)*2];
                const uint32_t* blp = &blf[nt >> 1][(nt & 1)*2];
                mma16816(acc[mt][nt], ah[mt], bhp);
                mma16816(acc[mt][nt], ah[mt], blp);
                mma16816(acc[mt][nt], al[mt], bhp);
            }
    }

    int g = lane >> 2, tig = lane & 3;
    #pragma unroll
    for (int mt = 0; mt < 2; mt++)
        #pragma unroll
        for (int half = 0; half < 2; half++){
            int gi = i0 + wm*32 + mt*16 + g + half*8;
            const float* Pr = P + ((size_t)(b*SS + gi)*HH + h)*RUSE;
            float* Lr = L + ((size_t)bh*SS + gi)*SS;
            #pragma unroll
            for (int nt = 0; nt < 4; nt++){
                int gj = j0 + wn*32 + nt*8 + tig*2;
                #pragma unroll
                for (int e = 0; e < 2; e++){
                    int j = gj + e;
                    if (j > gi) continue;
                    int off = j - gi;
                    if (off < -100) off = -100;
                    Lr[j] = acc[mt][nt][half*2 + e]*0.125f + Pr[off + 100]
                          + b0t[(size_t)(b*SS + j)*HH + h];
                }
            }
        }
}

// ---------------- softmax: fp32 in, bf16 hi/lo out --------------------------
__global__ void softmax_kernel(const float* __restrict__ L,
                               __nv_bfloat16* __restrict__ Ph,
                               __nv_bfloat16* __restrict__ Pl)
{
    int i = blockIdx.x;
    size_t ro = ((size_t)blockIdx.y*SS + i)*SS;
    const float* row = L + ro;
    int n = i + 1;
    int tid = threadIdx.x;
    float v[4];
    float mx = -1e30f;
    #pragma unroll
    for (int l = 0; l < 4; l++){
        int j = tid + l*128;
        v[l] = (j < n) ? row[j] : -1e30f;
        mx = fmaxf(mx, v[l]);
    }
    #pragma unroll
    for (int o = 16; o > 0; o >>= 1) mx = fmaxf(mx, __shfl_xor_sync(0xffffffffu, mx, o));
    __shared__ float smx[4], ssum[4];
    if ((tid & 31) == 0) smx[tid>>5] = mx;
    __syncthreads();
    mx = fmaxf(fmaxf(smx[0], smx[1]), fmaxf(smx[2], smx[3]));
    float s = 0.f;
    #pragma unroll
    for (int l = 0; l < 4; l++){
        int j = tid + l*128;
        if (j < n){ v[l] = __expf(v[l] - mx); s += v[l]; } else v[l] = 0.f;
    }
    #pragma unroll
    for (int o = 16; o > 0; o >>= 1) s += __shfl_xor_sync(0xffffffffu, s, o);
    if ((tid & 31) == 0) ssum[tid>>5] = s;
    __syncthreads();
    s = ssum[0] + ssum[1] + ssum[2] + ssum[3];
    float inv = 1.f / s;
    #pragma unroll
    for (int l = 0; l < 4; l++){
        int j = tid + l*128;
        float p = (j < n) ? v[l]*inv : 0.f;
        __nv_bfloat16 h = __float2bfloat16_rn(p);
        Ph[ro + j] = h;
        Pl[ro + j] = __float2bfloat16_rn(p - __bfloat162float(h));
    }
}

// ---------------- att via mma: scores @ kv + residual -----------------------
__device__ __forceinline__ void load_att_chunk(uint32_t stage, int tid,
    const __nv_bfloat16* __restrict__ Ph, const __nv_bfloat16* __restrict__ Pl,
    const __nv_bfloat16* __restrict__ kvh, const __nv_bfloat16* __restrict__ kvl,
    int bh, int b, int h, int i0, int jt)
{
    int j0 = jt*64;
    #pragma unroll
    for (int t = 0; t < 2; t++){
        const __nv_bfloat16* g = t ? Pl : Ph;
        uint32_t tb = stage + t*ATILE_B;
        #pragma unroll
        for (int i = 0; i < 4; i++){
            int s = i*128 + tid;
            int r = s >> 3, seg = s & 7;
            cpa16(tb + (uint32_t)(r*144 + seg*16),
                  g + ((size_t)bh*SS + i0 + r)*SS + j0 + seg*8, 16u);
        }
    }
    #pragma unroll
    for (int t = 0; t < 2; t++){
        const __nv_bfloat16* g = t ? kvl : kvh;
        uint32_t tb = stage + (2 + t)*ATILE_B;
        #pragma unroll
        for (int i = 0; i < 4; i++){
            int s = i*128 + tid;
            int r = s >> 3, seg = s & 7;
            cpa16(tb + (uint32_t)(r*144 + seg*16),
                  g + ((size_t)(b*SS + j0 + r))*EE + h*DD + seg*8, 16u);
        }
    }
    cpcommit();
}

__global__ __launch_bounds__(128) void att_mma(
    const __nv_bfloat16* __restrict__ Ph, const __nv_bfloat16* __restrict__ Pl,
    const __nv_bfloat16* __restrict__ kvh, const __nv_bfloat16* __restrict__ kvl,
    const float* __restrict__ vals, float* __restrict__ V)
{
    extern __shared__ char smem[];
    uint32_t sb = s2u(smem);
    int tid = threadIdx.x;
    int lane = tid & 31, warp = tid >> 5;
    int it = blockIdx.x, bh = blockIdx.y, b = bh >> 3, h = bh & 7;
    int i0 = it*64;
    int NCH = it + 1;

    int wm = warp >> 1, wn = warp & 1;
    int a_row  = wm*32 + (lane & 15);
    int a_col8 = (lane >> 4)*8;
    // trans-B (kv): lane -> row k (j) = k0 + (lane&15), col = n0 + ((lane&16)?8:0)
    int bt_row = lane & 15;
    int bt_col = wn*32 + ((lane & 16) ? 8 : 0);

    float acc[2][4][4];
    #pragma unroll
    for (int a = 0; a < 2; a++)
        #pragma unroll
        for (int bb2 = 0; bb2 < 4; bb2++)
            #pragma unroll
            for (int c = 0; c < 4; c++) acc[a][bb2][c] = 0.f;

    uint32_t st0 = sb, st1 = sb + ASTAGE_B;
    load_att_chunk(st0, tid, Ph, Pl, kvh, kvl, bh, b, h, i0, 0);

    for (int c = 0; c < NCH; c++){
        uint32_t cur = (c & 1) ? st1 : st0;
        if (c + 1 < NCH)
            load_att_chunk((c & 1) ? st0 : st1, tid, Ph, Pl, kvh, kvl, bh, b, h, i0, c + 1);
        if (c + 1 < NCH) cpwait1(); else cpwait0();
        __syncthreads();

        uint32_t cSh = cur, cSl = cur + ATILE_B, cKh = cur + 2*ATILE_B, cKl = cur + 3*ATILE_B;
        #pragma unroll
        for (int ks = 0; ks < 4; ks++){
            int k0 = ks*16;
            uint32_t ah[2][4], al[2][4], bhf[2][4], blf[2][4];
            #pragma unroll
            for (int mt = 0; mt < 2; mt++){
                uint32_t off = (uint32_t)(((a_row + mt*16)*ASTRIDE) + k0 + a_col8)*2u;
                ldsm4(ah[mt], cSh + off);
                ldsm4(al[mt], cSl + off);
            }
            #pragma unroll
            for (int grp = 0; grp < 2; grp++){
                uint32_t off = (uint32_t)(((k0 + bt_row)*ASTRIDE) + bt_col + grp*16)*2u;
                ldsm4t(bhf[grp], cKh + off);
                ldsm4t(blf[grp], cKl + off);
            }
            #pragma unroll
            for (int mt = 0; mt < 2; mt++)
                #pragma unroll
                for (int nt = 0; nt < 4; nt++){
                    const uint32_t* bhp = &bhf[nt >> 1][(nt & 1)*2];
                    const uint32_t* blp = &blf[nt >> 1][(nt & 1)*2];
                    mma16816(acc[mt][nt], ah[mt], bhp);
                    mma16816(acc[mt][nt], ah[mt], blp);
                    mma16816(acc[mt][nt], al[mt], bhp);
                }
        }
        __syncthreads();
    }

    int g = lane >> 2, tig = lane & 3;
    #pragma unroll
    for (int mt = 0; mt < 2; mt++)
        #pragma unroll
        for (int half = 0; half < 2; half++){
            int gi = i0 + wm*32 + mt*16 + g + half*8;
            #pragma unroll
            for (int nt = 0; nt < 4; nt++){
                int gd = wn*32 + nt*8 + tig*2;
                size_t o = ((size_t)(b*SS + gi))*EE + h*DD + gd;
                float2 rv = *(const float2*)&vals[o];
                *(float2*)&V[o] = make_float2(acc[mt][nt][half*2 + 0] + rv.x,
                                              acc[mt][nt][half*2 + 1] + rv.y);
            }
        }
}

// ---------------- fused weight conversion -----------------------------------
struct WTab {
    const float* W[7];
    __nv_bfloat16* Th[7];
    __nv_bfloat16* Tl[7];
    int K[7];
    int N[7];
    int off[8];
};

__global__ void convWT_all(WTab tab)
{
    __shared__ float t[32][33];
    int bid = blockIdx.x;
    int e = 0;
    #pragma unroll
    for (int i = 1; i < 7; i++) if (bid >= tab.off[i]) e = i;
    int local = bid - tab.off[e];
    const float* W = tab.W[e];
    __nv_bfloat16* Th = tab.Th[e];
    __nv_bfloat16* Tl = tab.Tl[e];
    int K = tab.K[e], N = tab.N[e];
    int ntiles = N >> 5;
    int kt = local / ntiles, ct = local - kt*ntiles;
    int by = kt*32, bx = ct*32;
    int lx = threadIdx.x & 31, ly = threadIdx.x >> 5;
    #pragma unroll
    for (int i = 0; i < 32; i += 8)
        t[ly + i][lx] = W[(size_t)(by + ly + i)*N + bx + lx];
    __syncthreads();
    #pragma unroll
    for (int i = 0; i < 32; i += 8){
        int n = bx + ly + i, k = by + lx;
        float x = t[lx][ly + i];
        __nv_bfloat16 h = __float2bfloat16_rn(x);
        Th[(size_t)n*K + k] = h;
        Tl[(size_t)n*K + k] = __float2bfloat16_rn(x - __bfloat162float(h));
    }
}

__global__ void convA(const float* __restrict__ X, __nv_bfloat16* __restrict__ H,
                      __nv_bfloat16* __restrict__ L, int n)
{
    int i = blockIdx.x*256 + threadIdx.x;
    if (i < n){
        float x = X[i];
        __nv_bfloat16 h = __float2bfloat16_rn(x);
        H[i] = h;
        L[i] = __float2bfloat16_rn(x - __bfloat162float(h));
    }
}

// ---------------- LayerNorm -> bf16 hi/lo -----------------------------------
__global__ void ln_bf16(const float* __restrict__ X, const float* __restrict__ g,
                        const float* __restrict__ bt,
                        __nv_bfloat16* __restrict__ Yh, __nv_bfloat16* __restrict__ Yl)
{
    int row = blockIdx.x;
    int tid = threadIdx.x;
    const float* x = X + (size_t)row*EE;
    float a = x[tid], c = x[tid + 256];
    float s  = a + c;
    float s2 = a*a + c*c;
    #pragma unroll
    for (int o = 16; o > 0; o >>= 1){
        s  += __shfl_xor_sync(0xffffffffu, s,  o);
        s2 += __shfl_xor_sync(0xffffffffu, s2, o);
    }
    __shared__ float sa[8], sbm[8];
    if ((tid & 31) == 0){ sa[tid>>5] = s; sbm[tid>>5] = s2; }
    __syncthreads();
    float ts = 0.f, ts2 = 0.f;
    #pragma unroll
    for (int w = 0; w < 8; w++){ ts += sa[w]; ts2 += sbm[w]; }
    float mean = ts * (1.f/512.f);
    float var  = ts2 * (1.f/512.f) - mean*mean;
    float r = rsqrtf(var + 1e-3f);
    float y0 = (a - mean)*r*g[tid]       + bt[tid];
    float y1 = (c - mean)*r*g[tid + 256] + bt[tid + 256];
    __nv_bfloat16 h0 = __float2bfloat16_rn(y0);
    __nv_bfloat16 h1 = __float2bfloat16_rn(y1);
    Yh[(size_t)row*EE + tid]       = h0;
    Yh[(size_t)row*EE + tid + 256] = h1;
    Yl[(size_t)row*EE + tid]       = __float2bfloat16_rn(y0 - __bfloat162float(h0));
    Yl[(size_t)row*EE + tid + 256] = __float2bfloat16_rn(y1 - __bfloat162float(h1));
}

// ---------------- tiny N=8 projection ---------------------------------------
__global__ void proj8(const float* __restrict__ X, const float* __restrict__ Wp,
                      const float* __restrict__ bp, float* __restrict__ Y)
{
    int row = blockIdx.x;
    int tid = threadIdx.x;
    int h = tid & 7, seg = tid >> 3;
    const float* x = X + (size_t)row*EE;
    float s = 0.f;
    #pragma unroll
    for (int k = 0; k < 16; k++){
        int kk = seg*16 + k;
        s += x[kk] * Wp[kk*HH + h];
    }
    __shared__ float sm[256];
    sm[tid] = s;
    __syncthreads();
    if (tid < 8){
        float acc = bp[tid];
        #pragma unroll
        for (int sg = 0; sg < 32; sg++) acc += sm[sg*8 + tid];
        Y[(size_t)row*HH + tid] = acc;
    }
}

// ---------------- P[m,h,r] --------------------------------------------------
__global__ __launch_bounds__(128) void pkernel(
    const float* __restrict__ q, const float* __restrict__ krt,
    const float* __restrict__ t1, float* __restrict__ P)
{
    int h = blockIdx.y;
    int m = blockIdx.x * 128 + threadIdx.x;
    float qr[64];
    const float4* qp = (const float4*)(q + (size_t)m*EE + h*DD);
    #pragma unroll
    for (int t = 0; t < 16; t++){
        float4 v = qp[t];
        qr[t*4+0]=v.x; qr[t*4+1]=v.y; qr[t*4+2]=v.z; qr[t*4+3]=v.w;
    }
    float* Pp = P + ((size_t)m*HH + h)*RUSE;
    const float* kbase = krt + h*DD;
    for (int r = 0; r < RUSE; r++){
        const float4* kp = (const float4*)(kbase + (size_t)r*EE);
        float acc = 0.f;
        #pragma unroll
        for (int t = 0; t < 16; t++){
            float4 k4 = __ldg(&kp[t]);
            acc += qr[t*4+0]*k4.x + qr[t*4+1]*k4.y + qr[t*4+2]*k4.z + qr[t*4+3]*k4.w;
        }
        Pp[r] = acc + t1[r*HH + h];
    }
}

// ---------------- launch ----------------------------------------------------
extern "C" void kernel_launch(void* const* d_in, const int* in_sizes, int n_in,
                              void* d_out, int out_size)
{
    const float* values  = (const float*)d_in[0];
    const float* rel_enc = (const float*)d_in[2];
    const float* ln0_g   = (const float*)d_in[3];
    const float* ln0_b   = (const float*)d_in[4];
    const float* w_b0    = (const float*)d_in[5];
    const float* b_b0    = (const float*)d_in[6];
    const float* wq      = (const float*)d_in[7];
    const float* bq      = (const float*)d_in[8];
    const float* wke     = (const float*)d_in[9];
    const float* bke     = (const float*)d_in[10];
    const float* wkv     = (const float*)d_in[11];
    const float* bkv     = (const float*)d_in[12];
    const float* wkr     = (const float*)d_in[13];
    const float* bkr     = (const float*)d_in[14];
    const float* wab0    = (const float*)d_in[15];
    const float* bab0    = (const float*)d_in[16];
    const float* wab1    = (const float*)d_in[17];
    const float* bab1    = (const float*)d_in[18];
    const float* ln1_g   = (const float*)d_in[19];
    const float* ln1_b   = (const float*)d_in[20];
    const float* w11     = (const float*)d_in[21];
    const float* b11     = (const float*)d_in[22];
    const float* w12     = (const float*)d_in[23];
    const float* b12     = (const float*)d_in[24];
    float* out = (float*)d_out;

    float *p_q,*p_ke,*p_kv,*p_krt,*p_t1,*p_b0t,*p_P,*p_L,*p_v;
    cudaGetSymbolAddress((void**)&p_q,   g_q);
    cudaGetSymbolAddress((void**)&p_ke,  g_ke);
    cudaGetSymbolAddress((void**)&p_kv,  g_kv);
    cudaGetSymbolAddress((void**)&p_krt, g_krt);
    cudaGetSymbolAddress((void**)&p_t1,  g_t1);
    cudaGetSymbolAddress((void**)&p_b0t, g_b0t);
    cudaGetSymbolAddress((void**)&p_P,   g_P);
    cudaGetSymbolAddress((void**)&p_L,   g_L);
    cudaGetSymbolAddress((void**)&p_v,   g_v);

    __nv_bfloat16 *xnh,*xnl,*xh,*xl,*vnh,*vnl,*h1h,*h1l,*reh,*rel;
    __nv_bfloat16 *qh,*ql,*keh,*kel,*kvh,*kvl,*Sh,*Sl;
    __nv_bfloat16 *wb0h,*wb0l,*wqh,*wql,*wkeh,*wkel,*wkvh,*wkvl,*wkrh,*wkrl,*w11h,*w11l,*w12h,*w12l;
    cudaGetSymbolAddress((void**)&xnh, g_xnh); cudaGetSymbolAddress((void**)&xnl, g_xnl);
    cudaGetSymbolAddress((void**)&xh,  g_xh);  cudaGetSymbolAddress((void**)&xl,  g_xl);
    cudaGetSymbolAddress((void**)&vnh, g_vnh); cudaGetSymbolAddress((void**)&vnl, g_vnl);
    cudaGetSymbolAddress((void**)&h1h, g_h1h); cudaGetSymbolAddress((void**)&h1l, g_h1l);
    cudaGetSymbolAddress((void**)&reh, g_reh); cudaGetSymbolAddress((void**)&rel, g_rel_);
    cudaGetSymbolAddress((void**)&qh,  g_qh);  cudaGetSymbolAddress((void**)&ql,  g_ql);
    cudaGetSymbolAddress((void**)&keh, g_keh); cudaGetSymbolAddress((void**)&kel, g_kel);
    cudaGetSymbolAddress((void**)&kvh, g_kvh); cudaGetSymbolAddress((void**)&kvl, g_kvl);
    cudaGetSymbolAddress((void**)&Sh,  g_Ph);  cudaGetSymbolAddress((void**)&Sl,  g_Pl);
    cudaGetSymbolAddress((void**)&wb0h, g_wb0h); cudaGetSymbolAddress((void**)&wb0l, g_wb0l);
    cudaGetSymbolAddress((void**)&wqh,  g_wqh);  cudaGetSymbolAddress((void**)&wql,  g_wql);
    cudaGetSymbolAddress((void**)&wkeh, g_wkeh); cudaGetSymbolAddress((void**)&wkel, g_wkel);
    cudaGetSymbolAddress((void**)&wkvh, g_wkvh); cudaGetSymbolAddress((void**)&wkvl, g_wkvl);
    cudaGetSymbolAddress((void**)&wkrh, g_wkrh); cudaGetSymbolAddress((void**)&wkrl, g_wkrl);
    cudaGetSymbolAddress((void**)&w11h, g_w11h); cudaGetSymbolAddress((void**)&w11l, g_w11l);
    cudaGetSymbolAddress((void**)&w12h, g_w12h); cudaGetSymbolAddress((void**)&w12l, g_w12l);

    cudaFuncSetAttribute(gemm_tc<0>,  cudaFuncAttributeMaxDynamicSharedMemorySize, GSMEM_BYTES);
    cudaFuncSetAttribute(gemm_tc<2>,  cudaFuncAttributeMaxDynamicSharedMemorySize, GSMEM_BYTES);
    cudaFuncSetAttribute(gemm_qkv_tc, cudaFuncAttributeMaxDynamicSharedMemorySize, GSMEM_BYTES);
    cudaFuncSetAttribute(gemm_big_relu, cudaFuncAttributeMaxDynamicSharedMemorySize, GSMEM2_BYTES);
    cudaFuncSetAttribute(att_mma, cudaFuncAttributeMaxDynamicSharedMemorySize, ATT_SMEM);

    WTab tab;
    tab.W[0]=w_b0; tab.Th[0]=wb0h; tab.Tl[0]=wb0l; tab.K[0]=EE;   tab.N[0]=HIDD;
    tab.W[1]=wq;   tab.Th[1]=wqh;  tab.Tl[1]=wql;  tab.K[1]=HIDD; tab.N[1]=EE;
    tab.W[2]=wke;  tab.Th[2]=wkeh; tab.Tl[2]=wkel; tab.K[2]=HIDD; tab.N[2]=EE;
    tab.W[3]=wkv;  tab.Th[3]=wkvh; tab.Tl[3]=wkvl; tab.K[3]=HIDD; tab.N[3]=EE;
    tab.W[4]=wkr;  tab.Th[4]=wkrh; tab.Tl[4]=wkrl; tab.K[4]=EE;   tab.N[4]=EE;
    tab.W[5]=w11;  tab.Th[5]=w11h; tab.Tl[5]=w11l; tab.K[5]=EE;   tab.N[5]=HIDD;
    tab.W[6]=w12;  tab.Th[6]=w12h; tab.Tl[6]=w12l; tab.K[6]=HIDD; tab.N[6]=EE;
    int total = 0;
    for (int i = 0; i < 7; i++){
        tab.off[i] = total;
        total += (tab.K[i]/32) * (tab.N[i]/32);
    }
    tab.off[7] = total;
    convWT_all<<<total, 256>>>(tab);
    convA<<<(RFULL*EE + 255)/256, 256>>>(rel_enc, reh, rel, RFULL*EE);

    // 1) LN0
    ln_bf16<<<MR, 256>>>(values, ln0_g, ln0_b, xnh, xnl);
    // 2) x = relu(xn @ w_b0 + b_b0)
    gemm_big_relu<<<dim3(HIDD/256, MR/128), 256, GSMEM2_BYTES>>>(
        xnh, xnl, wb0h, wb0l, b_b0, xh, xl, MR, HIDD, EE);
    // 3) q / ke / kv: fp32 + bf16 hi/lo
    gemm_qkv_tc<<<dim3(EE/128, MR/128, 3), 256, GSMEM_BYTES>>>(
        xh, xl, wqh, wql, wkeh, wkel, wkvh, wkvl, bq, bke, bkv,
        p_q, p_ke, p_kv, qh, ql, keh, kel, kvh, kvl, MR, EE, HIDD);
    // 4) kr_table
    gemm_tc<0><<<dim3(EE/128, 2), 256, GSMEM_BYTES>>>(
        reh, rel, wkrh, wkrl, bkr, nullptr, p_krt, nullptr, nullptr, RFULL, EE, EE);
    // 5) t1 / bias0
    proj8<<<RFULL, 256>>>(p_krt, wab1, bab1, p_t1);
    proj8<<<MR, 256>>>(p_ke, wab0, bab0, p_b0t);
    // 6) P
    pkernel<<<dim3(MR/128, HH), 128>>>(p_q, p_krt, p_t1, p_P);
    // 7) logits via mma (causal tiles only)
    logits_mma<<<dim3(36, BB*HH), 128>>>(qh, ql, keh, kel, p_P, p_b0t, p_L);
    // 8) softmax -> bf16 hi/lo scores
    softmax_kernel<<<dim3(SS, BB*HH), 128>>>(p_L, Sh, Sl);
    // 9) att via mma + residual
    att_mma<<<dim3(8, BB*HH), 128, ATT_SMEM>>>(Sh, Sl, kvh, kvl, values, p_v);
    // 10) LN1
    ln_bf16<<<MR, 256>>>(p_v, ln1_g, ln1_b, vnh, vnl);
    // 11) h1 = relu(vn @ w11 + b11)
    gemm_big_relu<<<dim3(HIDD/256, MR/128), 256, GSMEM2_BYTES>>>(
        vnh, vnl, w11h, w11l, b11, h1h, h1l, MR, HIDD, EE);
    // 12) out = v + h1 @ w12 + b12
    gemm_tc<2><<<dim3(EE/128, MR/128), 256, GSMEM_BYTES>>>(
        h1h, h1l, w12h, w12l, b12, p_v, out, nullptr, nullptr, MR, EE, HIDD);
}

// round 7
// speedup vs baseline: 2.2235x; 1.1159x over previous
#include <cuda_runtime.h>
#include <cuda_bf16.h>
#include <cstdint>
#include <cstddef>

#define BB 4
#define SS 512
#define EE 512
#define HIDD 2048
#define HH 8
#define DD 64
#define RFULL 201
#define RUSE 101
#define MR (BB*SS)   // 2048

// ---------------- fp32 scratch ----------------------------------------------
__device__ __align__(128) float g_q [MR*EE];
__device__ __align__(128) float g_ke[MR*EE];
__device__ __align__(128) float g_krt[RFULL*EE];
__device__ __align__(128) float g_t1[RFULL*HH];
__device__ __align__(128) float g_b0t[MR*HH];
__device__ __align__(128) float g_P[(size_t)MR*HH*RUSE];
__device__ __align__(128) float g_L[(size_t)BB*HH*SS*SS];
__device__ __align__(128) float g_v [MR*EE];

// ---------------- bf16 split scratch ----------------------------------------
__device__ __align__(128) __nv_bfloat16 g_xnh[MR*EE],   g_xnl[MR*EE];
__device__ __align__(128) __nv_bfloat16 g_xh [MR*HIDD], g_xl [MR*HIDD];
__device__ __align__(128) __nv_bfloat16 g_vnh[MR*EE],   g_vnl[MR*EE];
__device__ __align__(128) __nv_bfloat16 g_h1h[MR*HIDD], g_h1l[MR*HIDD];
__device__ __align__(128) __nv_bfloat16 g_reh[RFULL*EE + 64], g_rel_[RFULL*EE + 64];
__device__ __align__(128) __nv_bfloat16 g_qh [MR*EE], g_ql [MR*EE];
__device__ __align__(128) __nv_bfloat16 g_keh[MR*EE], g_kel[MR*EE];
__device__ __align__(128) __nv_bfloat16 g_kvh[MR*EE], g_kvl[MR*EE];
__device__ __align__(128) __nv_bfloat16 g_Sh[(size_t)BB*HH*SS*SS];
__device__ __align__(128) __nv_bfloat16 g_Sl[(size_t)BB*HH*SS*SS];
// weights, transposed to [N][K] and split; q/ke/kv concatenated to [1536][2048]
__device__ __align__(128) __nv_bfloat16 g_wb0h[HIDD*EE],    g_wb0l[HIDD*EE];
__device__ __align__(128) __nv_bfloat16 g_wqkvh[3*EE*HIDD], g_wqkvl[3*EE*HIDD];
__device__ __align__(128) __nv_bfloat16 g_wkrh[EE*EE],      g_wkrl[EE*EE];
__device__ __align__(128) __nv_bfloat16 g_w11h[HIDD*EE],    g_w11l[HIDD*EE];
__device__ __align__(128) __nv_bfloat16 g_w12h[EE*HIDD],    g_w12l[EE*HIDD];

// ---------------- PTX helpers -----------------------------------------------
__device__ __forceinline__ uint32_t s2u(const void* p){
    uint32_t a;
    asm("{ .reg .u64 t; cvta.to.shared.u64 t, %1; cvt.u32.u64 %0, t; }" : "=r"(a) : "l"(p));
    return a;
}
__device__ __forceinline__ void cpa16(uint32_t dst, const void* src, uint32_t sz){
    asm volatile("cp.async.cg.shared.global [%0], [%1], 16, %2;" :: "r"(dst), "l"(src), "r"(sz));
}
__device__ __forceinline__ void cpcommit(){ asm volatile("cp.async.commit_group;" ::: "memory"); }
__device__ __forceinline__ void cpwait0(){ asm volatile("cp.async.wait_group 0;" ::: "memory"); }
__device__ __forceinline__ void cpwait1(){ asm volatile("cp.async.wait_group 1;" ::: "memory"); }

__device__ __forceinline__ void ldsm4(uint32_t* r, uint32_t addr){
    asm volatile("ldmatrix.sync.aligned.m8n8.x4.shared.b16 {%0,%1,%2,%3}, [%4];"
        : "=r"(r[0]), "=r"(r[1]), "=r"(r[2]), "=r"(r[3]) : "r"(addr));
}
__device__ __forceinline__ void ldsm4t(uint32_t* r, uint32_t addr){
    asm volatile("ldmatrix.sync.aligned.m8n8.x4.trans.shared.b16 {%0,%1,%2,%3}, [%4];"
        : "=r"(r[0]), "=r"(r[1]), "=r"(r[2]), "=r"(r[3]) : "r"(addr));
}
__device__ __forceinline__ void mma16816(float* d, const uint32_t* a, const uint32_t* b){
    asm volatile("mma.sync.aligned.m16n8k16.row.col.f32.bf16.bf16.f32 "
        "{%0,%1,%2,%3}, {%4,%5,%6,%7}, {%8,%9}, {%0,%1,%2,%3};"
        : "+f"(d[0]), "+f"(d[1]), "+f"(d[2]), "+f"(d[3])
        : "r"(a[0]), "r"(a[1]), "r"(a[2]), "r"(a[3]), "r"(b[0]), "r"(b[1]));
}

// geometry: k-chunk 64, rows padded to 72 bf16 (144 B) -> conflict-free ldsm
#define KC 64
#define KSTRIDE 72
#define ROWB 144
#define TILE_B (128*ROWB)                // 18432 (128-row tile)
#define STAGE_B (4*TILE_B)               // 73728
#define GSMEM_BYTES (2*STAGE_B)          // 147456 (128x128)

#define TILE_A2 (128*ROWB)               // 18432
#define TILE_B2 (256*ROWB)               // 36864
#define STAGE_B2 (2*TILE_A2 + 2*TILE_B2) // 110592
#define GSMEM2_BYTES (2*STAGE_B2)        // 221184 (128x256)

// attention tiles: 64x64 bf16, stride 72
#define ATILE_B (64*ROWB)                // 9216
#define ASTAGE_B (4*ATILE_B)             // 36864
#define ATT_SMEM (2*ASTAGE_B)            // 73728

// ---------------- loaders ----------------------------------------------------
__device__ __forceinline__ void load_chunk128(uint32_t stage, int tid,
    const __nv_bfloat16* __restrict__ Ah, const __nv_bfloat16* __restrict__ Al,
    const __nv_bfloat16* __restrict__ Bh, const __nv_bfloat16* __restrict__ Bl,
    int m0, int n0, int k0, int M, int K)
{
    #pragma unroll
    for (int t = 0; t < 4; t++){
        const __nv_bfloat16* g = (t==0)?Ah:(t==1)?Al:(t==2)?Bh:Bl;
        int row0 = (t < 2) ? m0 : n0;
        uint32_t tb = stage + t*TILE_B;
        #pragma unroll
        for (int i = 0; i < 4; i++){
            int s = i*256 + tid;          // 0..1023
            int r = s >> 3, seg = s & 7;
            int gr = row0 + r;
            uint32_t sz = 16u;
            if (t < 2 && gr >= M){ sz = 0u; gr = M - 1; }
            cpa16(tb + (uint32_t)(r*ROWB + seg*16),
                  g + (size_t)gr*K + k0 + seg*8, sz);
        }
    }
    cpcommit();
}

__device__ __forceinline__ void load_chunk_big(uint32_t stage, int tid,
    const __nv_bfloat16* __restrict__ Ah, const __nv_bfloat16* __restrict__ Al,
    const __nv_bfloat16* __restrict__ Bh, const __nv_bfloat16* __restrict__ Bl,
    int m0, int n0, int k0, int K)
{
    #pragma unroll
    for (int t = 0; t < 2; t++){
        const __nv_bfloat16* g = t ? Al : Ah;
        uint32_t tb = stage + t*TILE_A2;
        #pragma unroll
        for (int i = 0; i < 4; i++){
            int s = i*256 + tid;
            int r = s >> 3, seg = s & 7;
            cpa16(tb + (uint32_t)(r*ROWB + seg*16),
                  g + (size_t)(m0 + r)*K + k0 + seg*8, 16u);
        }
    }
    #pragma unroll
    for (int t = 0; t < 2; t++){
        const __nv_bfloat16* g = t ? Bl : Bh;
        uint32_t tb = stage + 2*TILE_A2 + t*TILE_B2;
        #pragma unroll
        for (int i = 0; i < 8; i++){
            int s = i*256 + tid;          // 0..2047
            int r = s >> 3, seg = s & 7;
            cpa16(tb + (uint32_t)(r*ROWB + seg*16),
                  g + (size_t)(n0 + r)*K + k0 + seg*8, 16u);
        }
    }
    cpcommit();
}

// ---------------- 128x128 mainloop ------------------------------------------
__device__ __forceinline__ void mainloop128(uint32_t sb, int tid, int lane, int warp,
    const __nv_bfloat16* Ah, const __nv_bfloat16* Al,
    const __nv_bfloat16* Bh, const __nv_bfloat16* Bl,
    int m0, int n0, int M, int K, float acc[4][4][4])
{
    int a_row  = (warp >> 2)*64 + (lane & 15);
    int a_col8 = (lane >> 4)*8;
    int b_row  = (warp & 3)*32 + (lane & 7) + ((lane & 16) ? 8 : 0);
    int b_col8 = ((lane & 8) ? 8 : 0);

    const int NC = K / KC;
    uint32_t st0 = sb, st1 = sb + STAGE_B;
    load_chunk128(st0, tid, Ah, Al, Bh, Bl, m0, n0, 0, M, K);

    for (int c = 0; c < NC; c++){
        uint32_t cur = (c & 1) ? st1 : st0;
        if (c + 1 < NC)
            load_chunk128((c & 1) ? st0 : st1, tid, Ah, Al, Bh, Bl, m0, n0, (c+1)*KC, M, K);
        if (c + 1 < NC) cpwait1(); else cpwait0();
        __syncthreads();

        uint32_t cAh = cur, cAl = cur + TILE_B, cBh = cur + 2*TILE_B, cBl = cur + 3*TILE_B;
        #pragma unroll
        for (int ks = 0; ks < 4; ks++){
            int k0 = ks*16;
            uint32_t ah[4][4], al[4][4], bh[2][4], bl[2][4];
            #pragma unroll
            for (int mt = 0; mt < 4; mt++){
                uint32_t off = (uint32_t)((a_row + mt*16)*KSTRIDE + k0 + a_col8)*2u;
                ldsm4(ah[mt], cAh + off);
                ldsm4(al[mt], cAl + off);
            }
            #pragma unroll
            for (int p = 0; p < 2; p++){
                uint32_t off = (uint32_t)((b_row + p*16)*KSTRIDE + k0 + b_col8)*2u;
                ldsm4(bh[p], cBh + off);
                ldsm4(bl[p], cBl + off);
            }
            // pass 1: Ah*Bh  (independent sweep)
            #pragma unroll
            for (int mt = 0; mt < 4; mt++)
                #pragma unroll
                for (int nt = 0; nt < 4; nt++)
                    mma16816(acc[mt][nt], ah[mt], &bh[nt >> 1][(nt & 1)*2]);
            // pass 2: Ah*Bl
            #pragma unroll
            for (int mt = 0; mt < 4; mt++)
                #pragma unroll
                for (int nt = 0; nt < 4; nt++)
                    mma16816(acc[mt][nt], ah[mt], &bl[nt >> 1][(nt & 1)*2]);
            // pass 3: Al*Bh
            #pragma unroll
            for (int mt = 0; mt < 4; mt++)
                #pragma unroll
                for (int nt = 0; nt < 4; nt++)
                    mma16816(acc[mt][nt], al[mt], &bh[nt >> 1][(nt & 1)*2]);
        }
        __syncthreads();
    }
}

// EPI: 0 fp32+bias, 2 fp32+bias+res
template<int EPI>
__global__ __launch_bounds__(256, 1)
void gemm_tc(const __nv_bfloat16* Ah, const __nv_bfloat16* Al,
             const __nv_bfloat16* Bh, const __nv_bfloat16* Bl,
             const float* __restrict__ bias, const float* __restrict__ res,
             float* __restrict__ Cf, int M, int N, int K)
{
    extern __shared__ char smem[];
    uint32_t sb = s2u(smem);
    int tid = threadIdx.x, lane = tid & 31, warp = tid >> 5;
    int m0 = blockIdx.y*128, n0 = blockIdx.x*128;
    float acc[4][4][4];
    #pragma unroll
    for (int a = 0; a < 4; a++)
        #pragma unroll
        for (int b = 0; b < 4; b++)
            #pragma unroll
            for (int c = 0; c < 4; c++) acc[a][b][c] = 0.f;

    mainloop128(sb, tid, lane, warp, Ah, Al, Bh, Bl, m0, n0, M, K, acc);

    int g = lane >> 2, tig = lane & 3;
    int wm = warp >> 2, wn = warp & 3;
    #pragma unroll
    for (int mt = 0; mt < 4; mt++)
        #pragma unroll
        for (int half = 0; half < 2; half++){
            int row = m0 + wm*64 + mt*16 + g + half*8;
            if (row >= M) continue;
            #pragma unroll
            for (int nt = 0; nt < 4; nt++){
                int col = n0 + wn*32 + nt*8 + tig*2;
                float v0 = acc[mt][nt][half*2 + 0] + bias[col];
                float v1 = acc[mt][nt][half*2 + 1] + bias[col + 1];
                size_t o = (size_t)row*N + col;
                if (EPI == 2){
                    float2 rv = *(const float2*)&res[o];
                    v0 += rv.x; v1 += rv.y;
                }
                *(float2*)&Cf[o] = make_float2(v0, v1);
            }
        }
}

// ---------------- 128x256 mainloop ------------------------------------------
__device__ __forceinline__ void mainloop_big(uint32_t sb, int tid, int lane, int warp,
    const __nv_bfloat16* Ah, const __nv_bfloat16* Al,
    const __nv_bfloat16* Bh, const __nv_bfloat16* Bl,
    int m0, int n0, int K, float acc[4][8][4])
{
    int a_row  = (warp >> 2)*64 + (lane & 15);
    int a_col8 = (lane >> 4)*8;
    int b_rowb = (warp & 3)*64 + (lane & 7) + ((lane & 16) ? 8 : 0);
    int b_col8 = ((lane & 8) ? 8 : 0);

    const int NC = K / KC;
    uint32_t st0 = sb, st1 = sb + STAGE_B2;
    load_chunk_big(st0, tid, Ah, Al, Bh, Bl, m0, n0, 0, K);

    for (int c = 0; c < NC; c++){
        uint32_t cur = (c & 1) ? st1 : st0;
        if (c + 1 < NC)
            load_chunk_big((c & 1) ? st0 : st1, tid, Ah, Al, Bh, Bl, m0, n0, (c+1)*KC, K);
        if (c + 1 < NC) cpwait1(); else cpwait0();
        __syncthreads();

        uint32_t cAh = cur, cAl = cur + TILE_A2;
        uint32_t cBh = cur + 2*TILE_A2, cBl = cur + 2*TILE_A2 + TILE_B2;
        #pragma unroll
        for (int ks = 0; ks < 4; ks++){
            int k0 = ks*16;
            uint32_t ah[4][4], al[4][4];
            #pragma unroll
            for (int mt = 0; mt < 4; mt++){
                uint32_t off = (uint32_t)((a_row + mt*16)*KSTRIDE + k0 + a_col8)*2u;
                ldsm4(ah[mt], cAh + off);
                ldsm4(al[mt], cAl + off);
            }
            #pragma unroll
            for (int h2 = 0; h2 < 2; h2++){
                uint32_t bh[2][4], bl[2][4];
                #pragma unroll
                for (int p = 0; p < 2; p++){
                    uint32_t off = (uint32_t)((b_rowb + (h2*2 + p)*16)*KSTRIDE + k0 + b_col8)*2u;
                    ldsm4(bh[p], cBh + off);
                    ldsm4(bl[p], cBl + off);
                }
                // three independent sweeps (no back-to-back RAW on acc)
                #pragma unroll
                for (int mt = 0; mt < 4; mt++)
                    #pragma unroll
                    for (int j = 0; j < 4; j++)
                        mma16816(acc[mt][h2*4 + j], ah[mt], &bh[j >> 1][(j & 1)*2]);
                #pragma unroll
                for (int mt = 0; mt < 4; mt++)
                    #pragma unroll
                    for (int j = 0; j < 4; j++)
                        mma16816(acc[mt][h2*4 + j], ah[mt], &bl[j >> 1][(j & 1)*2]);
                #pragma unroll
                for (int mt = 0; mt < 4; mt++)
                    #pragma unroll
                    for (int j = 0; j < 4; j++)
                        mma16816(acc[mt][h2*4 + j], al[mt], &bh[j >> 1][(j & 1)*2]);
            }
        }
        __syncthreads();
    }
}

// relu -> bf16 hi/lo
__global__ __launch_bounds__(256, 1)
void gemm_big_relu(const __nv_bfloat16* Ah, const __nv_bfloat16* Al,
                   const __nv_bfloat16* Bh, const __nv_bfloat16* Bl,
                   const float* __restrict__ bias,
                   __nv_bfloat16* __restrict__ Ch, __nv_bfloat16* __restrict__ Cl,
                   int M, int N, int K)
{
    extern __shared__ char smem[];
    uint32_t sb = s2u(smem);
    int tid = threadIdx.x, lane = tid & 31, warp = tid >> 5;
    int m0 = blockIdx.y*128, n0 = blockIdx.x*256;
    float acc[4][8][4];
    #pragma unroll
    for (int a = 0; a < 4; a++)
        #pragma unroll
        for (int b = 0; b < 8; b++)
            #pragma unroll
            for (int c = 0; c < 4; c++) acc[a][b][c] = 0.f;

    mainloop_big(sb, tid, lane, warp, Ah, Al, Bh, Bl, m0, n0, K, acc);

    int g = lane >> 2, tig = lane & 3;
    int wm = warp >> 2, wn = warp & 3;
    #pragma unroll
    for (int mt = 0; mt < 4; mt++)
        #pragma unroll
        for (int half = 0; half < 2; half++){
            int row = m0 + wm*64 + mt*16 + g + half*8;
            #pragma unroll
            for (int nt8 = 0; nt8 < 8; nt8++){
                int col = n0 + wn*64 + nt8*8 + tig*2;
                float v0 = fmaxf(acc[mt][nt8][half*2 + 0] + bias[col],     0.f);
                float v1 = fmaxf(acc[mt][nt8][half*2 + 1] + bias[col + 1], 0.f);
                size_t o = (size_t)row*N + col;
                __nv_bfloat16 h0 = __float2bfloat16_rn(v0);
                __nv_bfloat16 h1 = __float2bfloat16_rn(v1);
                __nv_bfloat16 l0 = __float2bfloat16_rn(v0 - __bfloat162float(h0));
                __nv_bfloat16 l1 = __float2bfloat16_rn(v1 - __bfloat162float(h1));
                *(uint32_t*)((char*)Ch + o*2) =
                    (uint32_t)__bfloat16_as_ushort(h0) | ((uint32_t)__bfloat16_as_ushort(h1) << 16);
                *(uint32_t*)((char*)Cl + o*2) =
                    (uint32_t)__bfloat16_as_ushort(l0) | ((uint32_t)__bfloat16_as_ushort(l1) << 16);
            }
        }
}

// merged qkv: B = concatenated [1536][2048], outputs routed by n0>>9
__global__ __launch_bounds__(256, 1)
void gemm_qkv_big(const __nv_bfloat16* Ah, const __nv_bfloat16* Al,
                  const __nv_bfloat16* Bh, const __nv_bfloat16* Bl,
                  const float* b0, const float* b1, const float* b2,
                  float* f0, float* f1,
                  __nv_bfloat16* c0h, __nv_bfloat16* c0l,
                  __nv_bfloat16* c1h, __nv_bfloat16* c1l,
                  __nv_bfloat16* c2h, __nv_bfloat16* c2l,
                  int M, int K)
{
    extern __shared__ char smem[];
    uint32_t sb = s2u(smem);
    int tid = threadIdx.x, lane = tid & 31, warp = tid >> 5;
    int m0 = blockIdx.y*128, n0 = blockIdx.x*256;
    float acc[4][8][4];
    #pragma unroll
    for (int a = 0; a < 4; a++)
        #pragma unroll
        for (int b = 0; b < 8; b++)
            #pragma unroll
            for (int c = 0; c < 4; c++) acc[a][b][c] = 0.f;

    mainloop_big(sb, tid, lane, warp, Ah, Al, Bh, Bl, m0, n0, K, acc);

    int z = n0 >> 9;
    const float* bias = (z==0)?b0:(z==1)?b1:b2;
    float* Cf = (z==0)?f0:(z==1)?f1:nullptr;
    __nv_bfloat16* Ch = (z==0)?c0h:(z==1)?c1h:c2h;
    __nv_bfloat16* Cl = (z==0)?c0l:(z==1)?c1l:c2l;
    int n0l = n0 & 511;

    int g = lane >> 2, tig = lane & 3;
    int wm = warp >> 2, wn = warp & 3;
    #pragma unroll
    for (int mt = 0; mt < 4; mt++)
        #pragma unroll
        for (int half = 0; half < 2; half++){
            int row = m0 + wm*64 + mt*16 + g + half*8;
            #pragma unroll
            for (int nt8 = 0; nt8 < 8; nt8++){
                int col = n0l + wn*64 + nt8*8 + tig*2;
                float v0 = acc[mt][nt8][half*2 + 0] + bias[col];
                float v1 = acc[mt][nt8][half*2 + 1] + bias[col + 1];
                size_t o = (size_t)row*512 + col;
                if (Cf) *(float2*)&Cf[o] = make_float2(v0, v1);
                __nv_bfloat16 h0 = __float2bfloat16_rn(v0);
                __nv_bfloat16 h1 = __float2bfloat16_rn(v1);
                __nv_bfloat16 l0 = __float2bfloat16_rn(v0 - __bfloat162float(h0));
                __nv_bfloat16 l1 = __float2bfloat16_rn(v1 - __bfloat162float(h1));
                *(uint32_t*)((char*)Ch + o*2) =
                    (uint32_t)__bfloat16_as_ushort(h0) | ((uint32_t)__bfloat16_as_ushort(h1) << 16);
                *(uint32_t*)((char*)Cl + o*2) =
                    (uint32_t)__bfloat16_as_ushort(l0) | ((uint32_t)__bfloat16_as_ushort(l1) << 16);
            }
        }
}

// ---------------- logits via mma: causal 64x64 tiles ------------------------
__global__ __launch_bounds__(128) void logits_mma(
    const __nv_bfloat16* __restrict__ qh, const __nv_bfloat16* __restrict__ ql,
    const __nv_bfloat16* __restrict__ keh, const __nv_bfloat16* __restrict__ kel,
    const float* __restrict__ P, const float* __restrict__ b0t,
    float* __restrict__ L)
{
    __shared__ char lsm[ASTAGE_B];
    uint32_t sb = s2u(lsm);
    int tid = threadIdx.x, lane = tid & 31, warp = tid >> 5;
    int tri = blockIdx.x;
    int it = 0;
    while ((it + 1)*(it + 2)/2 <= tri) it++;
    int jt = tri - it*(it + 1)/2;
    int bh = blockIdx.y, b = bh >> 3, h = bh & 7;
    int i0 = it*64, j0 = jt*64;

    #pragma unroll
    for (int t = 0; t < 4; t++){
        const __nv_bfloat16* g = (t==0)?qh:(t==1)?ql:(t==2)?keh:kel;
        int row0 = (t < 2) ? i0 : j0;
        uint32_t tb = sb + t*ATILE_B;
        #pragma unroll
        for (int i = 0; i < 4; i++){
            int s = i*128 + tid;
            int r = s >> 3, seg = s & 7;
            cpa16(tb + (uint32_t)(r*ROWB + seg*16),
                  g + ((size_t)(b*SS + row0 + r))*EE + h*DD + seg*8, 16u);
        }
    }
    cpcommit(); cpwait0();
    __syncthreads();

    int wm = warp >> 1, wn = warp & 1;
    int a_row  = wm*32 + (lane & 15);
    int a_col8 = (lane >> 4)*8;
    int b_row  = wn*32 + (lane & 7) + ((lane & 16) ? 8 : 0);
    int b_col8 = ((lane & 8) ? 8 : 0);

    uint32_t cAh = sb, cAl = sb + ATILE_B, cBh = sb + 2*ATILE_B, cBl = sb + 3*ATILE_B;
    float acc[2][4][4];
    #pragma unroll
    for (int a = 0; a < 2; a++)
        #pragma unroll
        for (int bb2 = 0; bb2 < 4; bb2++)
            #pragma unroll
            for (int c = 0; c < 4; c++) acc[a][bb2][c] = 0.f;

    #pragma unroll
    for (int ks = 0; ks < 4; ks++){
        int k0 = ks*16;
        uint32_t ah[2][4], al[2][4], bhf[2][4], blf[2][4];
        #pragma unroll
        for (int mt = 0; mt < 2; mt++){
            uint32_t off = (uint32_t)((a_row + mt*16)*KSTRIDE + k0 + a_col8)*2u;
            ldsm4(ah[mt], cAh + off);
            ldsm4(al[mt], cAl + off);
        }
        #pragma unroll
        for (int p = 0; p < 2; p++){
            uint32_t off = (uint32_t)((b_row + p*16)*KSTRIDE + k0 + b_col8)*2u;
            ldsm4(bhf[p], cBh + off);
            ldsm4(blf[p], cBl + off);
        }
        #pragma unroll
        for (int mt = 0; mt < 2; mt++)
            #pragma unroll
            for (int nt = 0; nt < 4; nt++)
                mma16816(acc[mt][nt], ah[mt], &bhf[nt >> 1][(nt & 1)*2]);
        #pragma unroll
        for (int mt = 0; mt < 2; mt++)
            #pragma unroll
            for (int nt = 0; nt < 4; nt++)
                mma16816(acc[mt][nt], ah[mt], &blf[nt >> 1][(nt & 1)*2]);
        #pragma unroll
        for (int mt = 0; mt < 2; mt++)
            #pragma unroll
            for (int nt = 0; nt < 4; nt++)
                mma16816(acc[mt][nt], al[mt], &bhf[nt >> 1][(nt & 1)*2]);
    }

    int g = lane >> 2, tig = lane & 3;
    #pragma unroll
    for (int mt = 0; mt < 2; mt++)
        #pragma unroll
        for (int half = 0; half < 2; half++){
            int gi = i0 + wm*32 + mt*16 + g + half*8;
            const float* Pr = P + ((size_t)(b*SS + gi)*HH + h)*RUSE;
            float* Lr = L + ((size_t)bh*SS + gi)*SS;
            #pragma unroll
            for (int nt = 0; nt < 4; nt++){
                int gj = j0 + wn*32 + nt*8 + tig*2;
                #pragma unroll
                for (int e = 0; e < 2; e++){
                    int j = gj + e;
                    if (j > gi) continue;
                    int off = j - gi;
                    if (off < -100) off = -100;
                    Lr[j] = acc[mt][nt][half*2 + e]*0.125f + Pr[off + 100]
                          + b0t[(size_t)(b*SS + j)*HH + h];
                }
            }
        }
}

// ---------------- softmax: fp32 in, bf16 hi/lo out --------------------------
__global__ void softmax_kernel(const float* __restrict__ L,
                               __nv_bfloat16* __restrict__ Ph,
                               __nv_bfloat16* __restrict__ Pl)
{
    int i = blockIdx.x;
    size_t ro = ((size_t)blockIdx.y*SS + i)*SS;
    const float* row = L + ro;
    int n = i + 1;
    int tid = threadIdx.x;
    float v[4];
    float mx = -1e30f;
    #pragma unroll
    for (int l = 0; l < 4; l++){
        int j = tid + l*128;
        v[l] = (j < n) ? row[j] : -1e30f;
        mx = fmaxf(mx, v[l]);
    }
    #pragma unroll
    for (int o = 16; o > 0; o >>= 1) mx = fmaxf(mx, __shfl_xor_sync(0xffffffffu, mx, o));
    __shared__ float smx[4], ssum[4];
    if ((tid & 31) == 0) smx[tid>>5] = mx;
    __syncthreads();
    mx = fmaxf(fmaxf(smx[0], smx[1]), fmaxf(smx[2], smx[3]));
    float s = 0.f;
    #pragma unroll
    for (int l = 0; l < 4; l++){
        int j = tid + l*128;
        if (j < n){ v[l] = __expf(v[l] - mx); s += v[l]; } else v[l] = 0.f;
    }
    #pragma unroll
    for (int o = 16; o > 0; o >>= 1) s += __shfl_xor_sync(0xffffffffu, s, o);
    if ((tid & 31) == 0) ssum[tid>>5] = s;
    __syncthreads();
    s = ssum[0] + ssum[1] + ssum[2] + ssum[3];
    float inv = 1.f / s;
    #pragma unroll
    for (int l = 0; l < 4; l++){
        int j = tid + l*128;
        float p = (j < n) ? v[l]*inv : 0.f;
        __nv_bfloat16 h = __float2bfloat16_rn(p);
        Ph[ro + j] = h;
        Pl[ro + j] = __float2bfloat16_rn(p - __bfloat162float(h));
    }
}

// ---------------- att via mma ------------------------------------------------
__device__ __forceinline__ void load_att_chunk(uint32_t stage, int tid,
    const __nv_bfloat16* __restrict__ Ph, const __nv_bfloat16* __restrict__ Pl,
    const __nv_bfloat16* __restrict__ kvh, const __nv_bfloat16* __restrict__ kvl,
    int bh, int b, int h, int i0, int jt)
{
    int j0 = jt*64;
    #pragma unroll
    for (int t = 0; t < 2; t++){
        const __nv_bfloat16* g = t ? Pl : Ph;
        uint32_t tb = stage + t*ATILE_B;
        #pragma unroll
        for (int i = 0; i < 4; i++){
            int s = i*128 + tid;
            int r = s >> 3, seg = s & 7;
            cpa16(tb + (uint32_t)(r*ROWB + seg*16),
                  g + ((size_t)bh*SS + i0 + r)*SS + j0 + seg*8, 16u);
        }
    }
    #pragma unroll
    for (int t = 0; t < 2; t++){
        const __nv_bfloat16* g = t ? kvl : kvh;
        uint32_t tb = stage + (2 + t)*ATILE_B;
        #pragma unroll
        for (int i = 0; i < 4; i++){
            int s = i*128 + tid;
            int r = s >> 3, seg = s & 7;
            cpa16(tb + (uint32_t)(r*ROWB + seg*16),
                  g + ((size_t)(b*SS + j0 + r))*EE + h*DD + seg*8, 16u);
        }
    }
    cpcommit();
}

__global__ __launch_bounds__(128) void att_mma(
    const __nv_bfloat16* __restrict__ Ph, const __nv_bfloat16* __restrict__ Pl,
    const __nv_bfloat16* __restrict__ kvh, const __nv_bfloat16* __restrict__ kvl,
    const float* __restrict__ vals, float* __restrict__ V)
{
    extern __shared__ char smem[];
    uint32_t sb = s2u(smem);
    int tid = threadIdx.x, lane = tid & 31, warp = tid >> 5;
    int it = blockIdx.x, bh = blockIdx.y, b = bh >> 3, h = bh & 7;
    int i0 = it*64;
    int NCH = it + 1;

    int wm = warp >> 1, wn = warp & 1;
    int a_row  = wm*32 + (lane & 15);
    int a_col8 = (lane >> 4)*8;
    int bt_row = lane & 15;
    int bt_col = wn*32 + ((lane & 16) ? 8 : 0);

    float acc[2][4][4];
    #pragma unroll
    for (int a = 0; a < 2; a++)
        #pragma unroll
        for (int bb2 = 0; bb2 < 4; bb2++)
            #pragma unroll
            for (int c = 0; c < 4; c++) acc[a][bb2][c] = 0.f;

    uint32_t st0 = sb, st1 = sb + ASTAGE_B;
    load_att_chunk(st0, tid, Ph, Pl, kvh, kvl, bh, b, h, i0, 0);

    for (int c = 0; c < NCH; c++){
        uint32_t cur = (c & 1) ? st1 : st0;
        if (c + 1 < NCH)
            load_att_chunk((c & 1) ? st0 : st1, tid, Ph, Pl, kvh, kvl, bh, b, h, i0, c + 1);
        if (c + 1 < NCH) cpwait1(); else cpwait0();
        __syncthreads();

        uint32_t cSh = cur, cSl = cur + ATILE_B, cKh = cur + 2*ATILE_B, cKl = cur + 3*ATILE_B;
        #pragma unroll
        for (int ks = 0; ks < 4; ks++){
            int k0 = ks*16;
            uint32_t ah[2][4], al[2][4], bhf[2][4], blf[2][4];
            #pragma unroll
            for (int mt = 0; mt < 2; mt++){
                uint32_t off = (uint32_t)((a_row + mt*16)*KSTRIDE + k0 + a_col8)*2u;
                ldsm4(ah[mt], cSh + off);
                ldsm4(al[mt], cSl + off);
            }
            #pragma unroll
            for (int grp = 0; grp < 2; grp++){
                uint32_t off = (uint32_t)((k0 + bt_row)*KSTRIDE + bt_col + grp*16)*2u;
                ldsm4t(bhf[grp], cKh + off);
                ldsm4t(blf[grp], cKl + off);
            }
            #pragma unroll
            for (int mt = 0; mt < 2; mt++)
                #pragma unroll
                for (int nt = 0; nt < 4; nt++)
                    mma16816(acc[mt][nt], ah[mt], &bhf[nt >> 1][(nt & 1)*2]);
            #pragma unroll
            for (int mt = 0; mt < 2; mt++)
                #pragma unroll
                for (int nt = 0; nt < 4; nt++)
                    mma16816(acc[mt][nt], ah[mt], &blf[nt >> 1][(nt & 1)*2]);
            #pragma unroll
            for (int mt = 0; mt < 2; mt++)
                #pragma unroll
                for (int nt = 0; nt < 4; nt++)
                    mma16816(acc[mt][nt], al[mt], &bhf[nt >> 1][(nt & 1)*2]);
        }
        __syncthreads();
    }

    int g = lane >> 2, tig = lane & 3;
    #pragma unroll
    for (int mt = 0; mt < 2; mt++)
        #pragma unroll
        for (int half = 0; half < 2; half++){
            int gi = i0 + wm*32 + mt*16 + g + half*8;
            #pragma unroll
            for (int nt = 0; nt < 4; nt++){
                int gd = wn*32 + nt*8 + tig*2;
                size_t o = ((size_t)(b*SS + gi))*EE + h*DD + gd;
                float2 rv = *(const float2*)&vals[o];
                *(float2*)&V[o] = make_float2(acc[mt][nt][half*2 + 0] + rv.x,
                                              acc[mt][nt][half*2 + 1] + rv.y);
            }
        }
}

// ---------------- fused weight conversion -----------------------------------
struct WTab {
    const float* W[7];
    __nv_bfloat16* Th[7];
    __nv_bfloat16* Tl[7];
    int K[7];
    int N[7];
    int off[8];
};

__global__ void convWT_all(WTab tab)
{
    __shared__ float t[32][33];
    int bid = blockIdx.x;
    int e = 0;
    #pragma unroll
    for (int i = 1; i < 7; i++) if (bid >= tab.off[i]) e = i;
    int local = bid - tab.off[e];
    const float* W = tab.W[e];
    __nv_bfloat16* Th = tab.Th[e];
    __nv_bfloat16* Tl = tab.Tl[e];
    int K = tab.K[e], N = tab.N[e];
    int ntiles = N >> 5;
    int kt = local / ntiles, ct = local - kt*ntiles;
    int by = kt*32, bx = ct*32;
    int lx = threadIdx.x & 31, ly = threadIdx.x >> 5;
    #pragma unroll
    for (int i = 0; i < 32; i += 8)
        t[ly + i][lx] = W[(size_t)(by + ly + i)*N + bx + lx];
    __syncthreads();
    #pragma unroll
    for (int i = 0; i < 32; i += 8){
        int n = bx + ly + i, k = by + lx;
        float x = t[lx][ly + i];
        __nv_bfloat16 h = __float2bfloat16_rn(x);
        Th[(size_t)n*K + k] = h;
        Tl[(size_t)n*K + k] = __float2bfloat16_rn(x - __bfloat162float(h));
    }
}

__global__ void convA(const float* __restrict__ X, __nv_bfloat16* __restrict__ H,
                      __nv_bfloat16* __restrict__ L, int n)
{
    int i = blockIdx.x*256 + threadIdx.x;
    if (i < n){
        float x = X[i];
        __nv_bfloat16 h = __float2bfloat16_rn(x);
        H[i] = h;
        L[i] = __float2bfloat16_rn(x - __bfloat162float(h));
    }
}

// ---------------- LayerNorm -> bf16 hi/lo -----------------------------------
__global__ void ln_bf16(const float* __restrict__ X, const float* __restrict__ g,
                        const float* __restrict__ bt,
                        __nv_bfloat16* __restrict__ Yh, __nv_bfloat16* __restrict__ Yl)
{
    int row = blockIdx.x;
    int tid = threadIdx.x;
    const float* x = X + (size_t)row*EE;
    float a = x[tid], c = x[tid + 256];
    float s  = a + c;
    float s2 = a*a + c*c;
    #pragma unroll
    for (int o = 16; o > 0; o >>= 1){
        s  += __shfl_xor_sync(0xffffffffu, s,  o);
        s2 += __shfl_xor_sync(0xffffffffu, s2, o);
    }
    __shared__ float sa[8], sbm[8];
    if ((tid & 31) == 0){ sa[tid>>5] = s; sbm[tid>>5] = s2; }
    __syncthreads();
    float ts = 0.f, ts2 = 0.f;
    #pragma unroll
    for (int w = 0; w < 8; w++){ ts += sa[w]; ts2 += sbm[w]; }
    float mean = ts * (1.f/512.f);
    float var  = ts2 * (1.f/512.f) - mean*mean;
    float r = rsqrtf(var + 1e-3f);
    float y0 = (a - mean)*r*g[tid]       + bt[tid];
    float y1 = (c - mean)*r*g[tid + 256] + bt[tid + 256];
    __nv_bfloat16 h0 = __float2bfloat16_rn(y0);
    __nv_bfloat16 h1 = __float2bfloat16_rn(y1);
    Yh[(size_t)row*EE + tid]       = h0;
    Yh[(size_t)row*EE + tid + 256] = h1;
    Yl[(size_t)row*EE + tid]       = __float2bfloat16_rn(y0 - __bfloat162float(h0));
    Yl[(size_t)row*EE + tid + 256] = __float2bfloat16_rn(y1 - __bfloat162float(h1));
}

// ---------------- tiny N=8 projection ---------------------------------------
__global__ void proj8(const float* __restrict__ X, const float* __restrict__ Wp,
                      const float* __restrict__ bp, float* __restrict__ Y)
{
    int row = blockIdx.x;
    int tid = threadIdx.x;
    int h = tid & 7, seg = tid >> 3;
    const float* x = X + (size_t)row*EE;
    float s = 0.f;
    #pragma unroll
    for (int k = 0; k < 16; k++){
        int kk = seg*16 + k;
        s += x[kk] * Wp[kk*HH + h];
    }
    __shared__ float sm[256];
    sm[tid] = s;
    __syncthreads();
    if (tid < 8){
        float acc = bp[tid];
        #pragma unroll
        for (int sg = 0; sg < 32; sg++) acc += sm[sg*8 + tid];
        Y[(size_t)row*HH + tid] = acc;
    }
}

// ---------------- P[m,h,r] --------------------------------------------------
__global__ __launch_bounds__(128) void pkernel(
    const float* __restrict__ q, const float* __restrict__ krt,
    const float* __restrict__ t1, float* __restrict__ P)
{
    int h = blockIdx.y;
    int m = blockIdx.x * 128 + threadIdx.x;
    float qr[64];
    const float4* qp = (const float4*)(q + (size_t)m*EE + h*DD);
    #pragma unroll
    for (int t = 0; t < 16; t++){
        float4 v = qp[t];
        qr[t*4+0]=v.x; qr[t*4+1]=v.y; qr[t*4+2]=v.z; qr[t*4+3]=v.w;
    }
    float* Pp = P + ((size_t)m*HH + h)*RUSE;
    const float* kbase = krt + h*DD;
    for (int r = 0; r < RUSE; r++){
        const float4* kp = (const float4*)(kbase + (size_t)r*EE);
        float acc = 0.f;
        #pragma unroll
        for (int t = 0; t < 16; t++){
            float4 k4 = __ldg(&kp[t]);
            acc += qr[t*4+0]*k4.x + qr[t*4+1]*k4.y + qr[t*4+2]*k4.z + qr[t*4+3]*k4.w;
        }
        Pp[r] = acc + t1[r*HH + h];
    }
}

// ---------------- launch ----------------------------------------------------
extern "C" void kernel_launch(void* const* d_in, const int* in_sizes, int n_in,
                              void* d_out, int out_size)
{
    const float* values  = (const float*)d_in[0];
    const float* rel_enc = (const float*)d_in[2];
    const float* ln0_g   = (const float*)d_in[3];
    const float* ln0_b   = (const float*)d_in[4];
    const float* w_b0    = (const float*)d_in[5];
    const float* b_b0    = (const float*)d_in[6];
    const float* wq      = (const float*)d_in[7];
    const float* bq      = (const float*)d_in[8];
    const float* wke     = (const float*)d_in[9];
    const float* bke     = (const float*)d_in[10];
    const float* wkv     = (const float*)d_in[11];
    const float* bkv     = (const float*)d_in[12];
    const float* wkr     = (const float*)d_in[13];
    const float* bkr     = (const float*)d_in[14];
    const float* wab0    = (const float*)d_in[15];
    const float* bab0    = (const float*)d_in[16];
    const float* wab1    = (const float*)d_in[17];
    const float* bab1    = (const float*)d_in[18];
    const float* ln1_g   = (const float*)d_in[19];
    const float* ln1_b   = (const float*)d_in[20];
    const float* w11     = (const float*)d_in[21];
    const float* b11     = (const float*)d_in[22];
    const float* w12     = (const float*)d_in[23];
    const float* b12     = (const float*)d_in[24];
    float* out = (float*)d_out;

    float *p_q,*p_ke,*p_krt,*p_t1,*p_b0t,*p_P,*p_L,*p_v;
    cudaGetSymbolAddress((void**)&p_q,   g_q);
    cudaGetSymbolAddress((void**)&p_ke,  g_ke);
    cudaGetSymbolAddress((void**)&p_krt, g_krt);
    cudaGetSymbolAddress((void**)&p_t1,  g_t1);
    cudaGetSymbolAddress((void**)&p_b0t, g_b0t);
    cudaGetSymbolAddress((void**)&p_P,   g_P);
    cudaGetSymbolAddress((void**)&p_L,   g_L);
    cudaGetSymbolAddress((void**)&p_v,   g_v);

    __nv_bfloat16 *xnh,*xnl,*xh,*xl,*vnh,*vnl,*h1h,*h1l,*reh,*rel;
    __nv_bfloat16 *qh,*ql,*keh,*kel,*kvh,*kvl,*Sh,*Sl;
    __nv_bfloat16 *wb0h,*wb0l,*wqkvh,*wqkvl,*wkrh,*wkrl,*w11h,*w11l,*w12h,*w12l;
    cudaGetSymbolAddress((void**)&xnh, g_xnh); cudaGetSymbolAddress((void**)&xnl, g_xnl);
    cudaGetSymbolAddress((void**)&xh,  g_xh);  cudaGetSymbolAddress((void**)&xl,  g_xl);
    cudaGetSymbolAddress((void**)&vnh, g_vnh); cudaGetSymbolAddress((void**)&vnl, g_vnl);
    cudaGetSymbolAddress((void**)&h1h, g_h1h); cudaGetSymbolAddress((void**)&h1l, g_h1l);
    cudaGetSymbolAddress((void**)&reh, g_reh); cudaGetSymbolAddress((void**)&rel, g_rel_);
    cudaGetSymbolAddress((void**)&qh,  g_qh);  cudaGetSymbolAddress((void**)&ql,  g_ql);
    cudaGetSymbolAddress((void**)&keh, g_keh); cudaGetSymbolAddress((void**)&kel, g_kel);
    cudaGetSymbolAddress((void**)&kvh, g_kvh); cudaGetSymbolAddress((void**)&kvl, g_kvl);
    cudaGetSymbolAddress((void**)&Sh,  g_Sh);  cudaGetSymbolAddress((void**)&Sl,  g_Sl);
    cudaGetSymbolAddress((void**)&wb0h, g_wb0h);   cudaGetSymbolAddress((void**)&wb0l, g_wb0l);
    cudaGetSymbolAddress((void**)&wqkvh, g_wqkvh); cudaGetSymbolAddress((void**)&wqkvl, g_wqkvl);
    cudaGetSymbolAddress((void**)&wkrh, g_wkrh);   cudaGetSymbolAddress((void**)&wkrl, g_wkrl);
    cudaGetSymbolAddress((void**)&w11h, g_w11h);   cudaGetSymbolAddress((void**)&w11l, g_w11l);
    cudaGetSymbolAddress((void**)&w12h, g_w12h);   cudaGetSymbolAddress((void**)&w12l, g_w12l);

    cudaFuncSetAttribute(gemm_tc<0>,    cudaFuncAttributeMaxDynamicSharedMemorySize, GSMEM_BYTES);
    cudaFuncSetAttribute(gemm_tc<2>,    cudaFuncAttributeMaxDynamicSharedMemorySize, GSMEM_BYTES);
    cudaFuncSetAttribute(gemm_big_relu, cudaFuncAttributeMaxDynamicSharedMemorySize, GSMEM2_BYTES);
    cudaFuncSetAttribute(gemm_qkv_big,  cudaFuncAttributeMaxDynamicSharedMemorySize, GSMEM2_BYTES);
    cudaFuncSetAttribute(att_mma,       cudaFuncAttributeMaxDynamicSharedMemorySize, ATT_SMEM);

    WTab tab;
    tab.W[0]=w_b0; tab.Th[0]=wb0h;              tab.Tl[0]=wb0l;              tab.K[0]=EE;   tab.N[0]=HIDD;
    tab.W[1]=wq;   tab.Th[1]=wqkvh;             tab.Tl[1]=wqkvl;             tab.K[1]=HIDD; tab.N[1]=EE;
    tab.W[2]=wke;  tab.Th[2]=wqkvh + 512*HIDD;  tab.Tl[2]=wqkvl + 512*HIDD;  tab.K[2]=HIDD; tab.N[2]=EE;
    tab.W[3]=wkv;  tab.Th[3]=wqkvh + 1024*HIDD; tab.Tl[3]=wqkvl + 1024*HIDD; tab.K[3]=HIDD; tab.N[3]=EE;
    tab.W[4]=wkr;  tab.Th[4]=wkrh;              tab.Tl[4]=wkrl;              tab.K[4]=EE;   tab.N[4]=EE;
    tab.W[5]=w11;  tab.Th[5]=w11h;              tab.Tl[5]=w11l;              tab.K[5]=EE;   tab.N[5]=HIDD;
    tab.W[6]=w12;  tab.Th[6]=w12h;              tab.Tl[6]=w12l;              tab.K[6]=HIDD; tab.N[6]=EE;
    int total = 0;
    for (int i = 0; i < 7; i++){
        tab.off[i] = total;
        total += (tab.K[i]/32) * (tab.N[i]/32);
    }
    tab.off[7] = total;
    convWT_all<<<total, 256>>>(tab);
    convA<<<(RFULL*EE + 255)/256, 256>>>(rel_enc, reh, rel, RFULL*EE);

    // 1) LN0
    ln_bf16<<<MR, 256>>>(values, ln0_g, ln0_b, xnh, xnl);
    // 2) x = relu(xn @ w_b0 + b_b0)   [128x256, 128 blocks]
    gemm_big_relu<<<dim3(HIDD/256, MR/128), 256, GSMEM2_BYTES>>>(
        xnh, xnl, wb0h, wb0l, b_b0, xh, xl, MR, HIDD, EE);
    // 3) merged q/ke/kv               [128x256, 96 blocks = 1 wave]
    gemm_qkv_big<<<dim3(6, MR/128), 256, GSMEM2_BYTES>>>(
        xh, xl, wqkvh, wqkvl, bq, bke, bkv,
        p_q, p_ke, qh, ql, keh, kel, kvh, kvl, MR, HIDD);
    // 4) kr_table
    gemm_tc<0><<<dim3(EE/128, 2), 256, GSMEM_BYTES>>>(
        reh, rel, wkrh, wkrl, bkr, nullptr, p_krt, RFULL, EE, EE);
    // 5) t1 / bias0
    proj8<<<RFULL, 256>>>(p_krt, wab1, bab1, p_t1);
    proj8<<<MR, 256>>>(p_ke, wab0, bab0, p_b0t);
    // 6) P
    pkernel<<<dim3(MR/128, HH), 128>>>(p_q, p_krt, p_t1, p_P);
    // 7) logits
    logits_mma<<<dim3(36, BB*HH), 128>>>(qh, ql, keh, kel, p_P, p_b0t, p_L);
    // 8) softmax
    softmax_kernel<<<dim3(SS, BB*HH), 128>>>(p_L, Sh, Sl);
    // 9) att + residual
    att_mma<<<dim3(8, BB*HH), 128, ATT_SMEM>>>(Sh, Sl, kvh, kvl, values, p_v);
    // 10) LN1
    ln_bf16<<<MR, 256>>>(p_v, ln1_g, ln1_b, vnh, vnl);
    // 11) h1 = relu(vn @ w11 + b11)
    gemm_big_relu<<<dim3(HIDD/256, MR/128), 256, GSMEM2_BYTES>>>(
        vnh, vnl, w11h, w11l, b11, h1h, h1l, MR, HIDD, EE);
    // 12) out = v + h1 @ w12 + b12
    gemm_tc<2><<<dim3(EE/128, MR/128), 256, GSMEM_BYTES>>>(
        h1h, h1l, w12h, w12l, b12, p_v, out, MR, EE, HIDD);
}